// round 3
// baseline (speedup 1.0000x reference)
#include <cuda_runtime.h>
#include <cuda_bf16.h>

// Problem constants
#define BB 4
#define SS 2048
#define HH 2048
#define RR 64

#define KC 32                 // K-chunk for factor kernel
#define NCHUNK (2048 / KC)
#define AP  40                // smem row pitch (bf16 elems), factor kernel
#define AP3 72                // smem row pitch, output kernel

// Scratch: split bf16 factors. F_s stored [b][s][r], F_h stored transposed [b][r][h].
__device__ __align__(16) unsigned short g_Fs_hi[BB * SS * RR];
__device__ __align__(16) unsigned short g_Fs_lo[BB * SS * RR];
__device__ __align__(16) unsigned short g_Fh_hi[BB * RR * HH];
__device__ __align__(16) unsigned short g_Fh_lo[BB * RR * HH];

// ---------------------------------------------------------------------------
// Helpers
// ---------------------------------------------------------------------------

// Pack two floats to bf16x2 (low half = v0, high half = v1)
__device__ __forceinline__ unsigned pack2(float v0, float v1) {
    __nv_bfloat162 t = __floats2bfloat162_rn(v0, v1);
    return *reinterpret_cast<unsigned*>(&t);
}

// Two-term split of a pair of floats: h = bf16 hi parts packed, l = bf16 residuals packed
__device__ __forceinline__ void split_pair(float v0, float v1, unsigned& h, unsigned& l) {
    h = pack2(v0, v1);
    float h0 = __uint_as_float(h << 16);          // bf16(v0) as f32
    float h1 = __uint_as_float(h & 0xFFFF0000u);  // bf16(v1) as f32
    l = pack2(v0 - h0, v1 - h1);
}

__device__ __forceinline__ void split1(float v, unsigned short& h, unsigned short& l) {
    __nv_bfloat16 hb = __float2bfloat16(v);
    h = __bfloat16_as_ushort(hb);
    l = __bfloat16_as_ushort(__float2bfloat16(v - __bfloat162float(hb)));
}

__device__ __forceinline__ void mma_bf16(float c[4], const unsigned a[4], const unsigned b[2]) {
    asm volatile(
        "mma.sync.aligned.m16n8k16.row.col.f32.bf16.bf16.f32 "
        "{%0,%1,%2,%3}, {%4,%5,%6,%7}, {%8,%9}, {%0,%1,%2,%3};\n"
        : "+f"(c[0]), "+f"(c[1]), "+f"(c[2]), "+f"(c[3])
        : "r"(a[0]), "r"(a[1]), "r"(a[2]), "r"(a[3]), "r"(b[0]), "r"(b[1]));
}

// One k16 MMA step over a 64x64 CTA tile (warp tile 32x16 = 2x2 m16n8 frags),
// with 3-MMA bf16-split accumulation. Shared between both kernels.
template <int PITCH>
__device__ __forceinline__ void compute_k16(
    const unsigned short* __restrict__ As_h, const unsigned short* __restrict__ As_l,
    const unsigned short* __restrict__ Bs_h, const unsigned short* __restrict__ Bs_l,
    int kb, int mB, int nB, int g, int q, float acc[2][2][4])
{
    unsigned ah[2][4], al[2][4], bh[2][2], bl[2][2];
#pragma unroll
    for (int i = 0; i < 2; ++i) {
        int r0 = (mB + i * 16 + g) * PITCH + kb + 2 * q;
        int r8 = r0 + 8 * PITCH;
        ah[i][0] = *(const unsigned*)&As_h[r0];
        ah[i][1] = *(const unsigned*)&As_h[r8];
        ah[i][2] = *(const unsigned*)&As_h[r0 + 8];
        ah[i][3] = *(const unsigned*)&As_h[r8 + 8];
        al[i][0] = *(const unsigned*)&As_l[r0];
        al[i][1] = *(const unsigned*)&As_l[r8];
        al[i][2] = *(const unsigned*)&As_l[r0 + 8];
        al[i][3] = *(const unsigned*)&As_l[r8 + 8];
    }
#pragma unroll
    for (int j = 0; j < 2; ++j) {
        int n0 = (nB + j * 8 + g) * PITCH + kb + 2 * q;
        bh[j][0] = *(const unsigned*)&Bs_h[n0];
        bh[j][1] = *(const unsigned*)&Bs_h[n0 + 8];
        bl[j][0] = *(const unsigned*)&Bs_l[n0];
        bl[j][1] = *(const unsigned*)&Bs_l[n0 + 8];
    }
#pragma unroll
    for (int i = 0; i < 2; ++i)
#pragma unroll
        for (int j = 0; j < 2; ++j) {
            mma_bf16(acc[i][j], ah[i], bh[j]);
            mma_bf16(acc[i][j], ah[i], bl[j]);
            mma_bf16(acc[i][j], al[i], bh[j]);
        }
}

// ---------------------------------------------------------------------------
// Kernel 1: fused factor GEMMs.
//   blocks x in [0,32):  G1: F_s tile  = X_b[s0:s0+64, :] @ W_hid^T   (64 x 64, K=H)
//   blocks x in [32,64): G2: F_h^T tile = W_seq @ X_b[:, h0:h0+64]    (64 x 64, K=S)
// ---------------------------------------------------------------------------
__global__ void __launch_bounds__(256) fact_kernel(
    const float* __restrict__ X, const float* __restrict__ Wseq,
    const float* __restrict__ Whid)
{
    __shared__ unsigned short As_h[64 * AP], As_l[64 * AP];
    __shared__ unsigned short Bs_h[64 * AP], Bs_l[64 * AP];

    const int b   = blockIdx.z;
    const int tid = threadIdx.x;
    const bool isG1 = (blockIdx.x < 32);
    const int tile  = isG1 ? blockIdx.x : (blockIdx.x - 32);

    // A operand: row-major, K contiguous
    const float* Ag   = isG1 ? (X + ((long)b * SS + (long)tile * 64) * HH) : Wseq;
    const long aPitch = isG1 ? HH : SS;
    // B operand sources
    const float* BgW = Whid;                               // G1: B[k,n] = Whid[n,k] (k contiguous)
    const float* BgX = X + (long)b * SS * HH + tile * 64;  // G2: B[k,n] = X[b,k,h0+n] (n contiguous)

    const int arow = tid >> 3;           // staging row, 2 passes of 256 -> 64 rows
    const int ac4  = (tid & 7) * 4;      // k offset (float4)
    const int bkk  = tid >> 4;           // G2: k row
    const int bn4  = (tid & 15) * 4;     // G2: n offset (float4)

    float4 pa[2], pb[2];

    // prefetch chunk 0
#pragma unroll
    for (int r = 0; r < 2; ++r)
        pa[r] = *(const float4*)(Ag + (long)(arow + r * 32) * aPitch + ac4);
    if (isG1) {
#pragma unroll
        for (int r = 0; r < 2; ++r)
            pb[r] = *(const float4*)(BgW + (long)(arow + r * 32) * HH + ac4);
    } else {
#pragma unroll
        for (int r = 0; r < 2; ++r)
            pb[r] = *(const float4*)(BgX + (long)(bkk + r * 16) * HH + bn4);
    }

    const int warpId = tid >> 5, lane = tid & 31;
    const int mB = (warpId >> 2) * 32, nB = (warpId & 3) * 16;
    const int g = lane >> 2, q = lane & 3;

    float acc[2][2][4];
#pragma unroll
    for (int i = 0; i < 2; ++i)
#pragma unroll
        for (int j = 0; j < 2; ++j)
#pragma unroll
            for (int t = 0; t < 4; ++t) acc[i][j][t] = 0.0f;

    for (int kc = 0; kc < NCHUNK; ++kc) {
        // split + store prefetched chunk into smem
#pragma unroll
        for (int r = 0; r < 2; ++r) {
            int row = arow + r * 32;
            unsigned h0, l0, h1, l1;
            split_pair(pa[r].x, pa[r].y, h0, l0);
            split_pair(pa[r].z, pa[r].w, h1, l1);
            *(uint2*)&As_h[row * AP + ac4] = make_uint2(h0, h1);
            *(uint2*)&As_l[row * AP + ac4] = make_uint2(l0, l1);
        }
        if (isG1) {
#pragma unroll
            for (int r = 0; r < 2; ++r) {
                int row = arow + r * 32;
                unsigned h0, l0, h1, l1;
                split_pair(pb[r].x, pb[r].y, h0, l0);
                split_pair(pb[r].z, pb[r].w, h1, l1);
                *(uint2*)&Bs_h[row * AP + ac4] = make_uint2(h0, h1);
                *(uint2*)&Bs_l[row * AP + ac4] = make_uint2(l0, l1);
            }
        } else {
            // transpose staging: B[k,n] -> Bs[n][k]
#pragma unroll
            for (int r = 0; r < 2; ++r) {
                int kk = bkk + r * 16;
                float v[4] = {pb[r].x, pb[r].y, pb[r].z, pb[r].w};
#pragma unroll
                for (int j = 0; j < 4; ++j) {
                    unsigned short h, l;
                    split1(v[j], h, l);
                    Bs_h[(bn4 + j) * AP + kk] = h;
                    Bs_l[(bn4 + j) * AP + kk] = l;
                }
            }
        }
        __syncthreads();

        // prefetch next chunk (latency hidden by MMAs below)
        if (kc + 1 < NCHUNK) {
            int k0 = (kc + 1) * KC;
#pragma unroll
            for (int r = 0; r < 2; ++r)
                pa[r] = *(const float4*)(Ag + (long)(arow + r * 32) * aPitch + k0 + ac4);
            if (isG1) {
#pragma unroll
                for (int r = 0; r < 2; ++r)
                    pb[r] = *(const float4*)(BgW + (long)(arow + r * 32) * HH + k0 + ac4);
            } else {
#pragma unroll
                for (int r = 0; r < 2; ++r)
                    pb[r] = *(const float4*)(BgX + (long)(k0 + bkk + r * 16) * HH + bn4);
            }
        }

#pragma unroll
        for (int kb = 0; kb < KC; kb += 16)
            compute_k16<AP>(As_h, As_l, Bs_h, Bs_l, kb, mB, nB, g, q, acc);
        __syncthreads();
    }

    // epilogue: split fp32 results to hi/lo bf16 scratch
    unsigned short* oH = isG1 ? g_Fs_hi : g_Fh_hi;
    unsigned short* oL = isG1 ? g_Fs_lo : g_Fh_lo;
    const long base   = isG1 ? (((long)b * SS + (long)tile * 64) * RR)
                             : ((long)b * RR * HH + (long)tile * 64);
    const long rpitch = isG1 ? RR : HH;
#pragma unroll
    for (int i = 0; i < 2; ++i)
#pragma unroll
        for (int j = 0; j < 2; ++j) {
            int row = mB + i * 16 + g;
            int col = nB + j * 8 + 2 * q;
#pragma unroll
            for (int t = 0; t < 4; ++t) {
                int rr = row + (t >> 1) * 8;
                int cc = col + (t & 1);
                unsigned short h, l;
                split1(acc[i][j][t], h, l);
                oH[base + (long)rr * rpitch + cc] = h;
                oL[base + (long)rr * rpitch + cc] = l;
            }
        }
}

// ---------------------------------------------------------------------------
// Kernel 2: Out_b = F_s[b] (S x 64) @ F_h^T[b] (64 x H), fp32 output.
// CTA tile 64x64, K=64 fully resident in smem.
// ---------------------------------------------------------------------------
__global__ void __launch_bounds__(256) out_kernel(float* __restrict__ Out)
{
    __shared__ unsigned short As_h[64 * AP3], As_l[64 * AP3];
    __shared__ unsigned short Bs_h[64 * AP3], Bs_l[64 * AP3];

    const int b  = blockIdx.z;
    const int s0 = blockIdx.y * 64;
    const int h0 = blockIdx.x * 64;
    const int tid = threadIdx.x;

    {
        // A tile: F_s[b][s0+row][k], k contiguous (64 wide)
        const uint2* AHg = (const uint2*)(g_Fs_hi + ((long)b * SS + s0) * RR);
        const uint2* ALg = (const uint2*)(g_Fs_lo + ((long)b * SS + s0) * RR);
#pragma unroll
        for (int r = 0; r < 4; ++r) {
            int idx = tid + r * 256;   // 0..1023
            int row = idx >> 4;        // 16 uint2 (64 bf16) per row
            int c   = idx & 15;
            *(uint2*)&As_h[row * AP3 + c * 4] = AHg[row * 16 + c];
            *(uint2*)&As_l[row * AP3 + c * 4] = ALg[row * 16 + c];
        }
        // B tile: Fh^T[b][k][h0+n], n contiguous -> transpose into Bs[n][k]
        const unsigned short* BHg = g_Fh_hi + (long)b * RR * HH + h0;
        const unsigned short* BLg = g_Fh_lo + (long)b * RR * HH + h0;
#pragma unroll
        for (int r = 0; r < 4; ++r) {
            int idx = tid + r * 256;
            int k   = idx >> 4;
            int n4  = (idx & 15) * 4;
            uint2 vh = *(const uint2*)(BHg + (long)k * HH + n4);
            uint2 vl = *(const uint2*)(BLg + (long)k * HH + n4);
            const unsigned short* ph = (const unsigned short*)&vh;
            const unsigned short* pl = (const unsigned short*)&vl;
#pragma unroll
            for (int j = 0; j < 4; ++j) {
                Bs_h[(n4 + j) * AP3 + k] = ph[j];
                Bs_l[(n4 + j) * AP3 + k] = pl[j];
            }
        }
    }
    __syncthreads();

    const int warpId = tid >> 5, lane = tid & 31;
    const int mB = (warpId >> 2) * 32, nB = (warpId & 3) * 16;
    const int g = lane >> 2, q = lane & 3;

    float acc[2][2][4];
#pragma unroll
    for (int i = 0; i < 2; ++i)
#pragma unroll
        for (int j = 0; j < 2; ++j)
#pragma unroll
            for (int t = 0; t < 4; ++t) acc[i][j][t] = 0.0f;

#pragma unroll
    for (int kb = 0; kb < 64; kb += 16)
        compute_k16<AP3>(As_h, As_l, Bs_h, Bs_l, kb, mB, nB, g, q, acc);

    float* O = Out + ((long)b * SS + s0) * HH + h0;
#pragma unroll
    for (int i = 0; i < 2; ++i)
#pragma unroll
        for (int j = 0; j < 2; ++j) {
            int row = mB + i * 16 + g;
            int col = nB + j * 8 + 2 * q;
#pragma unroll
            for (int t = 0; t < 4; ++t) {
                int rr = row + (t >> 1) * 8;
                int cc = col + (t & 1);
                O[(long)rr * HH + cc] = acc[i][j][t];
            }
        }
}

// ---------------------------------------------------------------------------
// Launch: inputs per metadata order: hidden_states, grid_chw (unused), W_seq, W_hid
// ---------------------------------------------------------------------------
extern "C" void kernel_launch(void* const* d_in, const int* in_sizes, int n_in,
                              void* d_out, int out_size) {
    const float* X    = (const float*)d_in[0];
    const float* Wseq = (const float*)d_in[2];
    const float* Whid = (const float*)d_in[3];
    float* Out = (float*)d_out;

    fact_kernel<<<dim3(64, 1, BB), 256>>>(X, Wseq, Whid);
    out_kernel<<<dim3(HH / 64, SS / 64, BB), 256>>>(Out);
}

// round 4
// speedup vs baseline: 1.0083x; 1.0083x over previous
#include <cuda_runtime.h>
#include <cuda_bf16.h>

// Problem constants
#define BB 4
#define SS 2048
#define HH 2048
#define RR 64

#define KC 32                 // K-chunk for factor kernel
#define NCHUNK (2048 / KC)
#define AP  40                // smem row pitch (bf16 elems), factor kernel
#define AP3 72                // smem row pitch, output kernel

// Scratch: split bf16 factors. F_s stored [b][s][r], F_h stored transposed [b][r][h].
__device__ __align__(16) unsigned short g_Fs_hi[BB * SS * RR];
__device__ __align__(16) unsigned short g_Fs_lo[BB * SS * RR];
__device__ __align__(16) unsigned short g_Fh_hi[BB * RR * HH];
__device__ __align__(16) unsigned short g_Fh_lo[BB * RR * HH];

// ---------------------------------------------------------------------------
// Helpers
// ---------------------------------------------------------------------------

// Pack two floats to bf16x2 (low half = v0, high half = v1)
__device__ __forceinline__ unsigned pack2(float v0, float v1) {
    __nv_bfloat162 t = __floats2bfloat162_rn(v0, v1);
    return *reinterpret_cast<unsigned*>(&t);
}

// Two-term split of a pair of floats: h = bf16 hi parts packed, l = bf16 residuals packed
__device__ __forceinline__ void split_pair(float v0, float v1, unsigned& h, unsigned& l) {
    h = pack2(v0, v1);
    float h0 = __uint_as_float(h << 16);          // bf16(v0) as f32
    float h1 = __uint_as_float(h & 0xFFFF0000u);  // bf16(v1) as f32
    l = pack2(v0 - h0, v1 - h1);
}

__device__ __forceinline__ void split1(float v, unsigned short& h, unsigned short& l) {
    __nv_bfloat16 hb = __float2bfloat16(v);
    h = __bfloat16_as_ushort(hb);
    l = __bfloat16_as_ushort(__float2bfloat16(v - __bfloat162float(hb)));
}

__device__ __forceinline__ void mma_bf16(float c[4], const unsigned a[4], const unsigned b[2]) {
    asm volatile(
        "mma.sync.aligned.m16n8k16.row.col.f32.bf16.bf16.f32 "
        "{%0,%1,%2,%3}, {%4,%5,%6,%7}, {%8,%9}, {%0,%1,%2,%3};\n"
        : "+f"(c[0]), "+f"(c[1]), "+f"(c[2]), "+f"(c[3])
        : "r"(a[0]), "r"(a[1]), "r"(a[2]), "r"(a[3]), "r"(b[0]), "r"(b[1]));
}

// One k16 MMA step over a 64x64 CTA tile (warp tile 32x16 = 2x2 m16n8 frags),
// with 3-MMA bf16-split accumulation. Shared between both kernels.
template <int PITCH>
__device__ __forceinline__ void compute_k16(
    const unsigned short* __restrict__ As_h, const unsigned short* __restrict__ As_l,
    const unsigned short* __restrict__ Bs_h, const unsigned short* __restrict__ Bs_l,
    int kb, int mB, int nB, int g, int q, float acc[2][2][4])
{
    unsigned ah[2][4], al[2][4], bh[2][2], bl[2][2];
#pragma unroll
    for (int i = 0; i < 2; ++i) {
        int r0 = (mB + i * 16 + g) * PITCH + kb + 2 * q;
        int r8 = r0 + 8 * PITCH;
        ah[i][0] = *(const unsigned*)&As_h[r0];
        ah[i][1] = *(const unsigned*)&As_h[r8];
        ah[i][2] = *(const unsigned*)&As_h[r0 + 8];
        ah[i][3] = *(const unsigned*)&As_h[r8 + 8];
        al[i][0] = *(const unsigned*)&As_l[r0];
        al[i][1] = *(const unsigned*)&As_l[r8];
        al[i][2] = *(const unsigned*)&As_l[r0 + 8];
        al[i][3] = *(const unsigned*)&As_l[r8 + 8];
    }
#pragma unroll
    for (int j = 0; j < 2; ++j) {
        int n0 = (nB + j * 8 + g) * PITCH + kb + 2 * q;
        bh[j][0] = *(const unsigned*)&Bs_h[n0];
        bh[j][1] = *(const unsigned*)&Bs_h[n0 + 8];
        bl[j][0] = *(const unsigned*)&Bs_l[n0];
        bl[j][1] = *(const unsigned*)&Bs_l[n0 + 8];
    }
#pragma unroll
    for (int i = 0; i < 2; ++i)
#pragma unroll
        for (int j = 0; j < 2; ++j) {
            mma_bf16(acc[i][j], ah[i], bh[j]);
            mma_bf16(acc[i][j], ah[i], bl[j]);
            mma_bf16(acc[i][j], al[i], bh[j]);
        }
}

// ---------------------------------------------------------------------------
// Kernel 1: fused factor GEMMs.
//   blocks x in [0,32):  G1: F_s tile  = X_b[s0:s0+64, :] @ W_hid^T   (64 x 64, K=H)
//   blocks x in [32,64): G2: F_h^T tile = W_seq @ X_b[:, h0:h0+64]    (64 x 64, K=S)
// ---------------------------------------------------------------------------
__global__ void __launch_bounds__(256) fact_kernel(
    const float* __restrict__ X, const float* __restrict__ Wseq,
    const float* __restrict__ Whid)
{
    __shared__ unsigned short As_h[64 * AP], As_l[64 * AP];
    __shared__ unsigned short Bs_h[64 * AP], Bs_l[64 * AP];

    const int b   = blockIdx.z;
    const int tid = threadIdx.x;
    const bool isG1 = (blockIdx.x < 32);
    const int tile  = isG1 ? blockIdx.x : (blockIdx.x - 32);

    // A operand: row-major, K contiguous
    const float* Ag   = isG1 ? (X + ((long)b * SS + (long)tile * 64) * HH) : Wseq;
    const long aPitch = isG1 ? HH : SS;
    // B operand sources
    const float* BgW = Whid;                               // G1: B[k,n] = Whid[n,k] (k contiguous)
    const float* BgX = X + (long)b * SS * HH + tile * 64;  // G2: B[k,n] = X[b,k,h0+n] (n contiguous)

    const int arow = tid >> 3;           // staging row, 2 passes of 256 -> 64 rows
    const int ac4  = (tid & 7) * 4;      // k offset (float4)
    const int bkk  = tid >> 4;           // G2: k row
    const int bn4  = (tid & 15) * 4;     // G2: n offset (float4)

    float4 pa[2], pb[2];

    // prefetch chunk 0
#pragma unroll
    for (int r = 0; r < 2; ++r)
        pa[r] = *(const float4*)(Ag + (long)(arow + r * 32) * aPitch + ac4);
    if (isG1) {
#pragma unroll
        for (int r = 0; r < 2; ++r)
            pb[r] = *(const float4*)(BgW + (long)(arow + r * 32) * HH + ac4);
    } else {
#pragma unroll
        for (int r = 0; r < 2; ++r)
            pb[r] = *(const float4*)(BgX + (long)(bkk + r * 16) * HH + bn4);
    }

    const int warpId = tid >> 5, lane = tid & 31;
    const int mB = (warpId >> 2) * 32, nB = (warpId & 3) * 16;
    const int g = lane >> 2, q = lane & 3;

    float acc[2][2][4];
#pragma unroll
    for (int i = 0; i < 2; ++i)
#pragma unroll
        for (int j = 0; j < 2; ++j)
#pragma unroll
            for (int t = 0; t < 4; ++t) acc[i][j][t] = 0.0f;

    for (int kc = 0; kc < NCHUNK; ++kc) {
        // split + store prefetched chunk into smem
#pragma unroll
        for (int r = 0; r < 2; ++r) {
            int row = arow + r * 32;
            unsigned h0, l0, h1, l1;
            split_pair(pa[r].x, pa[r].y, h0, l0);
            split_pair(pa[r].z, pa[r].w, h1, l1);
            *(uint2*)&As_h[row * AP + ac4] = make_uint2(h0, h1);
            *(uint2*)&As_l[row * AP + ac4] = make_uint2(l0, l1);
        }
        if (isG1) {
#pragma unroll
            for (int r = 0; r < 2; ++r) {
                int row = arow + r * 32;
                unsigned h0, l0, h1, l1;
                split_pair(pb[r].x, pb[r].y, h0, l0);
                split_pair(pb[r].z, pb[r].w, h1, l1);
                *(uint2*)&Bs_h[row * AP + ac4] = make_uint2(h0, h1);
                *(uint2*)&Bs_l[row * AP + ac4] = make_uint2(l0, l1);
            }
        } else {
            // transpose staging: B[k,n] -> Bs[n][k]
#pragma unroll
            for (int r = 0; r < 2; ++r) {
                int kk = bkk + r * 16;
                float v[4] = {pb[r].x, pb[r].y, pb[r].z, pb[r].w};
#pragma unroll
                for (int j = 0; j < 4; ++j) {
                    unsigned short h, l;
                    split1(v[j], h, l);
                    Bs_h[(bn4 + j) * AP + kk] = h;
                    Bs_l[(bn4 + j) * AP + kk] = l;
                }
            }
        }
        __syncthreads();

        // prefetch next chunk (latency hidden by MMAs below)
        if (kc + 1 < NCHUNK) {
            int k0 = (kc + 1) * KC;
#pragma unroll
            for (int r = 0; r < 2; ++r)
                pa[r] = *(const float4*)(Ag + (long)(arow + r * 32) * aPitch + k0 + ac4);
            if (isG1) {
#pragma unroll
                for (int r = 0; r < 2; ++r)
                    pb[r] = *(const float4*)(BgW + (long)(arow + r * 32) * HH + k0 + ac4);
            } else {
#pragma unroll
                for (int r = 0; r < 2; ++r)
                    pb[r] = *(const float4*)(BgX + (long)(k0 + bkk + r * 16) * HH + bn4);
            }
        }

#pragma unroll
        for (int kb = 0; kb < KC; kb += 16)
            compute_k16<AP>(As_h, As_l, Bs_h, Bs_l, kb, mB, nB, g, q, acc);
        __syncthreads();
    }

    // epilogue: split fp32 results to hi/lo bf16 scratch
    unsigned short* oH = isG1 ? g_Fs_hi : g_Fh_hi;
    unsigned short* oL = isG1 ? g_Fs_lo : g_Fh_lo;
    const long base   = isG1 ? (((long)b * SS + (long)tile * 64) * RR)
                             : ((long)b * RR * HH + (long)tile * 64);
    const long rpitch = isG1 ? RR : HH;
#pragma unroll
    for (int i = 0; i < 2; ++i)
#pragma unroll
        for (int j = 0; j < 2; ++j) {
            int row = mB + i * 16 + g;
            int col = nB + j * 8 + 2 * q;
#pragma unroll
            for (int t = 0; t < 4; ++t) {
                int rr = row + (t >> 1) * 8;
                int cc = col + (t & 1);
                unsigned short h, l;
                split1(acc[i][j][t], h, l);
                oH[base + (long)rr * rpitch + cc] = h;
                oL[base + (long)rr * rpitch + cc] = l;
            }
        }
}

// ---------------------------------------------------------------------------
// Kernel 2: Out_b = F_s[b] (S x 64) @ F_h^T[b] (64 x H), fp32 output.
// CTA tile 64x64, K=64 fully resident in smem.
// ---------------------------------------------------------------------------
__global__ void __launch_bounds__(256) out_kernel(float* __restrict__ Out)
{
    __shared__ unsigned short As_h[64 * AP3], As_l[64 * AP3];
    __shared__ unsigned short Bs_h[64 * AP3], Bs_l[64 * AP3];

    const int b  = blockIdx.z;
    const int s0 = blockIdx.y * 64;
    const int h0 = blockIdx.x * 64;
    const int tid = threadIdx.x;

    {
        // A tile: F_s[b][s0+row][k], k contiguous (64 wide)
        const uint2* AHg = (const uint2*)(g_Fs_hi + ((long)b * SS + s0) * RR);
        const uint2* ALg = (const uint2*)(g_Fs_lo + ((long)b * SS + s0) * RR);
#pragma unroll
        for (int r = 0; r < 4; ++r) {
            int idx = tid + r * 256;   // 0..1023
            int row = idx >> 4;        // 16 uint2 (64 bf16) per row
            int c   = idx & 15;
            *(uint2*)&As_h[row * AP3 + c * 4] = AHg[row * 16 + c];
            *(uint2*)&As_l[row * AP3 + c * 4] = ALg[row * 16 + c];
        }
        // B tile: Fh^T[b][k][h0+n], n contiguous -> transpose into Bs[n][k]
        const unsigned short* BHg = g_Fh_hi + (long)b * RR * HH + h0;
        const unsigned short* BLg = g_Fh_lo + (long)b * RR * HH + h0;
#pragma unroll
        for (int r = 0; r < 4; ++r) {
            int idx = tid + r * 256;
            int k   = idx >> 4;
            int n4  = (idx & 15) * 4;
            uint2 vh = *(const uint2*)(BHg + (long)k * HH + n4);
            uint2 vl = *(const uint2*)(BLg + (long)k * HH + n4);
            const unsigned short* ph = (const unsigned short*)&vh;
            const unsigned short* pl = (const unsigned short*)&vl;
#pragma unroll
            for (int j = 0; j < 4; ++j) {
                Bs_h[(n4 + j) * AP3 + k] = ph[j];
                Bs_l[(n4 + j) * AP3 + k] = pl[j];
            }
        }
    }
    __syncthreads();

    const int warpId = tid >> 5, lane = tid & 31;
    const int mB = (warpId >> 2) * 32, nB = (warpId & 3) * 16;
    const int g = lane >> 2, q = lane & 3;

    float acc[2][2][4];
#pragma unroll
    for (int i = 0; i < 2; ++i)
#pragma unroll
        for (int j = 0; j < 2; ++j)
#pragma unroll
            for (int t = 0; t < 4; ++t) acc[i][j][t] = 0.0f;

#pragma unroll
    for (int kb = 0; kb < 64; kb += 16)
        compute_k16<AP3>(As_h, As_l, Bs_h, Bs_l, kb, mB, nB, g, q, acc);

    float* O = Out + ((long)b * SS + s0) * HH + h0;
#pragma unroll
    for (int i = 0; i < 2; ++i)
#pragma unroll
        for (int j = 0; j < 2; ++j) {
            int row = mB + i * 16 + g;
            int col = nB + j * 8 + 2 * q;
#pragma unroll
            for (int t = 0; t < 4; ++t) {
                int rr = row + (t >> 1) * 8;
                int cc = col + (t & 1);
                O[(long)rr * HH + cc] = acc[i][j][t];
            }
        }
}

// ---------------------------------------------------------------------------
// Launch: inputs per metadata order: hidden_states, grid_chw (unused), W_seq, W_hid
// ---------------------------------------------------------------------------
extern "C" void kernel_launch(void* const* d_in, const int* in_sizes, int n_in,
                              void* d_out, int out_size) {
    const float* X    = (const float*)d_in[0];
    const float* Wseq = (const float*)d_in[2];
    const float* Whid = (const float*)d_in[3];
    float* Out = (float*)d_out;

    fact_kernel<<<dim3(64, 1, BB), 256>>>(X, Wseq, Whid);
    out_kernel<<<dim3(HH / 64, SS / 64, BB), 256>>>(Out);
}

// round 5
// speedup vs baseline: 1.1573x; 1.1478x over previous
#include <cuda_runtime.h>
#include <cuda_bf16.h>

#define BB 4
#define SS 2048
#define HH 2048
#define RR 64

// ---------------------------------------------------------------------------
// Global scratch (static device arrays; no runtime allocation).
// Split bf16 representations: v = hi + lo (each bf16), product via 3 MMAs.
// ---------------------------------------------------------------------------
__device__ __align__(16) unsigned short g_Xh[BB * SS * HH];   // 33.5 MB
__device__ __align__(16) unsigned short g_Xl[BB * SS * HH];
__device__ __align__(16) unsigned short g_Wsh[RR * SS];
__device__ __align__(16) unsigned short g_Wsl[RR * SS];
__device__ __align__(16) unsigned short g_Whh[RR * HH];
__device__ __align__(16) unsigned short g_Whl[RR * HH];
__device__ __align__(16) unsigned short g_Fsh[BB * SS * RR];  // F_s [b][s][r]
__device__ __align__(16) unsigned short g_Fsl[BB * SS * RR];
__device__ __align__(16) unsigned short g_Fhh[BB * RR * HH];  // F_h^T [b][r][h]
__device__ __align__(16) unsigned short g_Fhl[BB * RR * HH];

// ---------------------------------------------------------------------------
// Helpers
// ---------------------------------------------------------------------------
__device__ __forceinline__ unsigned pack2(float v0, float v1) {
    __nv_bfloat162 t = __floats2bfloat162_rn(v0, v1);
    return *reinterpret_cast<unsigned*>(&t);
}

__device__ __forceinline__ void split_pair(float v0, float v1, unsigned& h, unsigned& l) {
    h = pack2(v0, v1);
    float h0 = __uint_as_float(h << 16);
    float h1 = __uint_as_float(h & 0xFFFF0000u);
    l = pack2(v0 - h0, v1 - h1);
}

__device__ __forceinline__ void mma_bf16(float c[4], const unsigned a[4], const unsigned b[2]) {
    asm volatile(
        "mma.sync.aligned.m16n8k16.row.col.f32.bf16.bf16.f32 "
        "{%0,%1,%2,%3}, {%4,%5,%6,%7}, {%8,%9}, {%0,%1,%2,%3};\n"
        : "+f"(c[0]), "+f"(c[1]), "+f"(c[2]), "+f"(c[3])
        : "r"(a[0]), "r"(a[1]), "r"(a[2]), "r"(a[3]), "r"(b[0]), "r"(b[1]));
}

__device__ __forceinline__ void ldsm4(unsigned* r, unsigned a) {
    asm volatile("ldmatrix.sync.aligned.m8n8.x4.shared.b16 {%0,%1,%2,%3}, [%4];\n"
                 : "=r"(r[0]), "=r"(r[1]), "=r"(r[2]), "=r"(r[3]) : "r"(a));
}
__device__ __forceinline__ void ldsm4t(unsigned* r, unsigned a) {
    asm volatile("ldmatrix.sync.aligned.m8n8.x4.trans.shared.b16 {%0,%1,%2,%3}, [%4];\n"
                 : "=r"(r[0]), "=r"(r[1]), "=r"(r[2]), "=r"(r[3]) : "r"(a));
}

// ---------------------------------------------------------------------------
// Kernel 0: split fp32 tensor -> hi/lo bf16 scratch. mode: 0=X, 1=Wseq, 2=Whid
// ---------------------------------------------------------------------------
__global__ void __launch_bounds__(256) split_kernel(const float4* __restrict__ src,
                                                    int n4, int mode) {
    uint2* dh;
    uint2* dl;
    if (mode == 0)      { dh = (uint2*)g_Xh;  dl = (uint2*)g_Xl;  }
    else if (mode == 1) { dh = (uint2*)g_Wsh; dl = (uint2*)g_Wsl; }
    else                { dh = (uint2*)g_Whh; dl = (uint2*)g_Whl; }
    for (int i = blockIdx.x * 256 + threadIdx.x; i < n4; i += gridDim.x * 256) {
        float4 v = src[i];
        unsigned h0, l0, h1, l1;
        split_pair(v.x, v.y, h0, l0);
        split_pair(v.z, v.w, h1, l1);
        dh[i] = make_uint2(h0, h1);
        dl[i] = make_uint2(l0, l1);
    }
}

// ---------------------------------------------------------------------------
// Kernel 1: fused factor GEMMs (all-bf16 inputs, ldmatrix fragments).
//   blocks x in [0,32):  G1: F_s tile  = X_b[s0:+64, :] @ Whid^T  (A=[m][k], B=[n][k])
//   blocks x in [32,64): G2: F_h^T tile = Wseq @ X_b[:, h0:+64]   (A=[m][k], B=[k][n] -> trans)
// CTA tile 64x64, K chunk 64, 8 warps (warp 32x16).
// ---------------------------------------------------------------------------
#define FP 72  // smem pitch (shorts): 144B = 9*16B -> conflict-free ldmatrix

__global__ void __launch_bounds__(256) fact_kernel() {
    __shared__ unsigned short Ah[64 * FP], Al[64 * FP], Bh[64 * FP], Bl[64 * FP];

    const int b = blockIdx.z, tid = threadIdx.x;
    const bool isG1 = (blockIdx.x < 32);
    const int tile = isG1 ? blockIdx.x : blockIdx.x - 32;

    // staging map: row = tid&63, kg8 = 8*(tid>>6); each thread: 16B at kg8 and kg8+32
    const int row = tid & 63, kg8 = (tid >> 6) * 8;

    const unsigned short *pAh, *pAl, *pBh, *pBl;
    long sB;
    if (isG1) {
        long aoff = ((long)(b * SS + tile * 64 + row)) * HH + kg8;
        pAh = g_Xh + aoff;  pAl = g_Xl + aoff;
        long boff = (long)row * HH + kg8;
        pBh = g_Whh + boff; pBl = g_Whl + boff;
        sB = 64;
    } else {
        long aoff = (long)row * SS + kg8;
        pAh = g_Wsh + aoff; pAl = g_Wsl + aoff;
        long boff = ((long)(b * SS + row)) * HH + tile * 64 + kg8;
        pBh = g_Xh + boff;  pBl = g_Xl + boff;
        sB = (long)64 * HH;
    }

    // prefetch chunk 0
    uint4 rah0 = *(const uint4*)pAh, rah1 = *(const uint4*)(pAh + 32);
    uint4 ral0 = *(const uint4*)pAl, ral1 = *(const uint4*)(pAl + 32);
    uint4 rbh0 = *(const uint4*)pBh, rbh1 = *(const uint4*)(pBh + 32);
    uint4 rbl0 = *(const uint4*)pBl, rbl1 = *(const uint4*)(pBl + 32);

    const int warpId = tid >> 5, lane = tid & 31;
    const int mB = (warpId >> 2) * 32, nB = (warpId & 3) * 16;

    const unsigned sAh = (unsigned)__cvta_generic_to_shared(Ah);
    const unsigned sAl = (unsigned)__cvta_generic_to_shared(Al);
    const unsigned sBh = (unsigned)__cvta_generic_to_shared(Bh);
    const unsigned sBl = (unsigned)__cvta_generic_to_shared(Bl);

    // A fragment addressing ([m][k]): lanes 0-7 rows@k0, 8-15 rows+8@k0, 16-23 rows@k8, 24-31 rows+8@k8
    const unsigned aoffA = 2 * ((mB + (lane & 15)) * FP + (lane >> 4) * 8);
    const unsigned aAddrH = sAh + aoffA, aAddrL = sAl + aoffA;
    unsigned bAddrH, bAddrL;
    if (isG1) {  // B layout [n][k]
        const unsigned off = 2 * ((nB + (lane & 7) + ((lane & 16) >> 1)) * FP + (lane & 8));
        bAddrH = sBh + off; bAddrL = sBl + off;
    } else {     // B layout [k][n] (A-style rows = k), read via ldmatrix.trans
        const unsigned off = 2 * ((lane & 15) * FP + nB + (lane >> 4) * 8);
        bAddrH = sBh + off; bAddrL = sBl + off;
    }

    float acc[2][2][4];
#pragma unroll
    for (int i = 0; i < 2; ++i)
#pragma unroll
        for (int j = 0; j < 2; ++j)
#pragma unroll
            for (int t = 0; t < 4; ++t) acc[i][j][t] = 0.0f;

    for (int kc = 0; kc < 32; ++kc) {
        // stage prefetched chunk
        *(uint4*)&Ah[row * FP + kg8]      = rah0;
        *(uint4*)&Ah[row * FP + kg8 + 32] = rah1;
        *(uint4*)&Al[row * FP + kg8]      = ral0;
        *(uint4*)&Al[row * FP + kg8 + 32] = ral1;
        *(uint4*)&Bh[row * FP + kg8]      = rbh0;
        *(uint4*)&Bh[row * FP + kg8 + 32] = rbh1;
        *(uint4*)&Bl[row * FP + kg8]      = rbl0;
        *(uint4*)&Bl[row * FP + kg8 + 32] = rbl1;
        __syncthreads();

        if (kc < 31) {
            pAh += 64; pAl += 64; pBh += sB; pBl += sB;
            rah0 = *(const uint4*)pAh; rah1 = *(const uint4*)(pAh + 32);
            ral0 = *(const uint4*)pAl; ral1 = *(const uint4*)(pAl + 32);
            rbh0 = *(const uint4*)pBh; rbh1 = *(const uint4*)(pBh + 32);
            rbl0 = *(const uint4*)pBl; rbl1 = *(const uint4*)(pBl + 32);
        }

#pragma unroll
        for (int kb = 0; kb < 64; kb += 16) {
            unsigned ah[2][4], al[2][4], bhf[4], blf[4];
            ldsm4(ah[0], aAddrH + kb * 2);
            ldsm4(ah[1], aAddrH + kb * 2 + 16 * FP * 2);
            ldsm4(al[0], aAddrL + kb * 2);
            ldsm4(al[1], aAddrL + kb * 2 + 16 * FP * 2);
            if (isG1) {
                ldsm4(bhf, bAddrH + kb * 2);
                ldsm4(blf, bAddrL + kb * 2);
            } else {
                ldsm4t(bhf, bAddrH + kb * (FP * 2));
                ldsm4t(blf, bAddrL + kb * (FP * 2));
            }
#pragma unroll
            for (int i = 0; i < 2; ++i)
#pragma unroll
                for (int j = 0; j < 2; ++j) {
                    mma_bf16(acc[i][j], ah[i], &bhf[2 * j]);
                    mma_bf16(acc[i][j], ah[i], &blf[2 * j]);
                    mma_bf16(acc[i][j], al[i], &bhf[2 * j]);
                }
        }
        __syncthreads();
    }

    // epilogue: split fp32 tile to hi/lo bf16 factor scratch (packed 32-bit stores)
    const int g = lane >> 2, q = lane & 3;
    unsigned short *oH, *oL;
    long base, pitch;
    if (isG1) { oH = g_Fsh; oL = g_Fsl; base = ((long)(b * SS + tile * 64)) * RR; pitch = RR; }
    else      { oH = g_Fhh; oL = g_Fhl; base = (long)b * RR * HH + tile * 64;     pitch = HH; }
#pragma unroll
    for (int i = 0; i < 2; ++i)
#pragma unroll
        for (int j = 0; j < 2; ++j) {
            int r0 = mB + i * 16 + g;
            int c  = nB + j * 8 + 2 * q;
            unsigned hp, lp;
            split_pair(acc[i][j][0], acc[i][j][1], hp, lp);
            *(unsigned*)&oH[base + (long)r0 * pitch + c] = hp;
            *(unsigned*)&oL[base + (long)r0 * pitch + c] = lp;
            split_pair(acc[i][j][2], acc[i][j][3], hp, lp);
            *(unsigned*)&oH[base + (long)(r0 + 8) * pitch + c] = hp;
            *(unsigned*)&oL[base + (long)(r0 + 8) * pitch + c] = lp;
        }
}

// ---------------------------------------------------------------------------
// Kernel 2: Out_b = F_s[b] (S x 64) @ F_h^T[b] (64 x H), fp32 out.
// CTA tile 128x128, K=64 resident, 8 warps (warp 64x32), dynamic smem.
// ---------------------------------------------------------------------------
#define OAP 72    // A pitch (shorts)
#define OBP 136   // B pitch (shorts): 272B = 17*16B -> conflict-free trans ldmatrix
#define OSM_AL (128 * OAP)
#define OSM_BH (2 * 128 * OAP)
#define OSM_BL (2 * 128 * OAP + 64 * OBP)
#define OSM_TOT_BYTES ((2 * 128 * OAP + 2 * 64 * OBP) * 2)  // 71680

__global__ void __launch_bounds__(256) out_kernel(float* __restrict__ Out) {
    extern __shared__ unsigned short sm[];
    unsigned short* Ah = sm;
    unsigned short* Al = sm + OSM_AL;
    unsigned short* Bh = sm + OSM_BH;
    unsigned short* Bl = sm + OSM_BL;

    const int b = blockIdx.z, s0 = blockIdx.y * 128, h0 = blockIdx.x * 128;
    const int tid = threadIdx.x;

    // stage A: 128 rows x 64 k (contiguous), B: 64 rows(k) x 128 n (contiguous)
    {
        const unsigned short* gh = g_Fsh + ((long)(b * SS + s0)) * RR;
        const unsigned short* gl = g_Fsl + ((long)(b * SS + s0)) * RR;
#pragma unroll
        for (int p = 0; p < 4; ++p) {
            int idx = tid + p * 256;
            int r = idx >> 3, c = (idx & 7) * 8;
            *(uint4*)&Ah[r * OAP + c] = *(const uint4*)&gh[r * RR + c];
            *(uint4*)&Al[r * OAP + c] = *(const uint4*)&gl[r * RR + c];
        }
        const unsigned short* bhg = g_Fhh + (long)b * RR * HH + h0;
        const unsigned short* blg = g_Fhl + (long)b * RR * HH + h0;
#pragma unroll
        for (int p = 0; p < 4; ++p) {
            int idx = tid + p * 256;
            int r = idx >> 4, c = (idx & 15) * 8;
            *(uint4*)&Bh[r * OBP + c] = *(const uint4*)&bhg[(long)r * HH + c];
            *(uint4*)&Bl[r * OBP + c] = *(const uint4*)&blg[(long)r * HH + c];
        }
    }
    __syncthreads();

    const int warpId = tid >> 5, lane = tid & 31;
    const int mB = (warpId >> 2) * 64, nB = (warpId & 3) * 32;

    const unsigned sAh = (unsigned)__cvta_generic_to_shared(Ah);
    const unsigned sAl = (unsigned)__cvta_generic_to_shared(Al);
    const unsigned sBh = (unsigned)__cvta_generic_to_shared(Bh);
    const unsigned sBl = (unsigned)__cvta_generic_to_shared(Bl);

    const unsigned aoff = 2 * ((mB + (lane & 15)) * OAP + (lane >> 4) * 8);
    const unsigned aH = sAh + aoff, aL = sAl + aoff;
    const unsigned boff = 2 * ((lane & 15) * OBP + nB + (lane >> 4) * 8);
    const unsigned bH = sBh + boff, bL = sBl + boff;

    float acc[4][4][4];
#pragma unroll
    for (int i = 0; i < 4; ++i)
#pragma unroll
        for (int j = 0; j < 4; ++j)
#pragma unroll
            for (int t = 0; t < 4; ++t) acc[i][j][t] = 0.0f;

#pragma unroll
    for (int kb = 0; kb < 64; kb += 16) {
        unsigned bhf[2][4], blf[2][4];
        ldsm4t(bhf[0], bH + kb * (OBP * 2));
        ldsm4t(bhf[1], bH + kb * (OBP * 2) + 16 * 2);
        ldsm4t(blf[0], bL + kb * (OBP * 2));
        ldsm4t(blf[1], bL + kb * (OBP * 2) + 16 * 2);
#pragma unroll
        for (int i = 0; i < 4; ++i) {
            unsigned ah[4], al[4];
            ldsm4(ah, aH + kb * 2 + i * (16 * OAP * 2));
            ldsm4(al, aL + kb * 2 + i * (16 * OAP * 2));
#pragma unroll
            for (int j = 0; j < 4; ++j) {
                const unsigned* bhp = &bhf[j >> 1][(j & 1) * 2];
                const unsigned* blp = &blf[j >> 1][(j & 1) * 2];
                mma_bf16(acc[i][j], ah, bhp);
                mma_bf16(acc[i][j], ah, blp);
                mma_bf16(acc[i][j], al, bhp);
            }
        }
    }

    const int g = lane >> 2, q = lane & 3;
    float* O = Out + ((long)(b * SS + s0)) * HH + h0;
#pragma unroll
    for (int i = 0; i < 4; ++i)
#pragma unroll
        for (int j = 0; j < 4; ++j) {
            int r = mB + i * 16 + g;
            int c = nB + j * 8 + 2 * q;
            *(float2*)&O[(long)r * HH + c]       = make_float2(acc[i][j][0], acc[i][j][1]);
            *(float2*)&O[(long)(r + 8) * HH + c] = make_float2(acc[i][j][2], acc[i][j][3]);
        }
}

// ---------------------------------------------------------------------------
// Launch: inputs per metadata: hidden_states, grid_chw (unused), W_seq, W_hid
// ---------------------------------------------------------------------------
extern "C" void kernel_launch(void* const* d_in, const int* in_sizes, int n_in,
                              void* d_out, int out_size) {
    const float* X    = (const float*)d_in[0];
    const float* Wseq = (const float*)d_in[2];
    const float* Whid = (const float*)d_in[3];
    float* Out = (float*)d_out;

    cudaFuncSetAttribute(out_kernel, cudaFuncAttributeMaxDynamicSharedMemorySize,
                         OSM_TOT_BYTES);

    split_kernel<<<4096, 256>>>((const float4*)X,    BB * SS * HH / 4, 0);
    split_kernel<<<128,  256>>>((const float4*)Wseq, RR * SS / 4,      1);
    split_kernel<<<128,  256>>>((const float4*)Whid, RR * HH / 4,      2);
    fact_kernel<<<dim3(64, 1, BB), 256>>>();
    out_kernel<<<dim3(HH / 128, SS / 128, BB), 256, OSM_TOT_BYTES>>>(Out);
}

// round 6
// speedup vs baseline: 1.2426x; 1.0737x over previous
#include <cuda_runtime.h>
#include <cuda_bf16.h>

#define BB 4
#define SS 2048
#define HH 2048
#define RR 64
#define KSPLIT 8
#define KPER (2048 / KSPLIT)   // 256 per CTA

// ---------------------------------------------------------------------------
// Global scratch (static device arrays; no runtime allocation).
// Split bf16 representations: v = hi + lo (each bf16), product via 3 MMAs.
// ---------------------------------------------------------------------------
__device__ __align__(16) unsigned short g_Xh[BB * SS * HH];   // 33.5 MB
__device__ __align__(16) unsigned short g_Xl[BB * SS * HH];
__device__ __align__(16) unsigned short g_Wsh[RR * SS];
__device__ __align__(16) unsigned short g_Wsl[RR * SS];
__device__ __align__(16) unsigned short g_Whh[RR * HH];
__device__ __align__(16) unsigned short g_Whl[RR * HH];
__device__ __align__(16) unsigned short g_Fsh[BB * SS * RR];  // F_s [b][s][r]
__device__ __align__(16) unsigned short g_Fsl[BB * SS * RR];
__device__ __align__(16) unsigned short g_Fhh[BB * RR * HH];  // F_h^T [b][r][h]
__device__ __align__(16) unsigned short g_Fhl[BB * RR * HH];
// split-K fp32 partials: [gb(8)][tile(32)][ksplit(8)][64*64]
__device__ __align__(16) float g_part[8 * 32 * KSPLIT * 64 * 64];  // 33.5 MB

// ---------------------------------------------------------------------------
// Helpers
// ---------------------------------------------------------------------------
__device__ __forceinline__ unsigned pack2(float v0, float v1) {
    __nv_bfloat162 t = __floats2bfloat162_rn(v0, v1);
    return *reinterpret_cast<unsigned*>(&t);
}

__device__ __forceinline__ void split_pair(float v0, float v1, unsigned& h, unsigned& l) {
    h = pack2(v0, v1);
    float h0 = __uint_as_float(h << 16);
    float h1 = __uint_as_float(h & 0xFFFF0000u);
    l = pack2(v0 - h0, v1 - h1);
}

__device__ __forceinline__ void mma_bf16(float c[4], const unsigned a[4], const unsigned b[2]) {
    asm volatile(
        "mma.sync.aligned.m16n8k16.row.col.f32.bf16.bf16.f32 "
        "{%0,%1,%2,%3}, {%4,%5,%6,%7}, {%8,%9}, {%0,%1,%2,%3};\n"
        : "+f"(c[0]), "+f"(c[1]), "+f"(c[2]), "+f"(c[3])
        : "r"(a[0]), "r"(a[1]), "r"(a[2]), "r"(a[3]), "r"(b[0]), "r"(b[1]));
}

__device__ __forceinline__ void ldsm4(unsigned* r, unsigned a) {
    asm volatile("ldmatrix.sync.aligned.m8n8.x4.shared.b16 {%0,%1,%2,%3}, [%4];\n"
                 : "=r"(r[0]), "=r"(r[1]), "=r"(r[2]), "=r"(r[3]) : "r"(a));
}
__device__ __forceinline__ void ldsm4t(unsigned* r, unsigned a) {
    asm volatile("ldmatrix.sync.aligned.m8n8.x4.trans.shared.b16 {%0,%1,%2,%3}, [%4];\n"
                 : "=r"(r[0]), "=r"(r[1]), "=r"(r[2]), "=r"(r[3]) : "r"(a));
}

// ---------------------------------------------------------------------------
// Kernel 0: split fp32 tensor -> hi/lo bf16 scratch. mode: 0=X, 1=Wseq, 2=Whid
// ---------------------------------------------------------------------------
__global__ void __launch_bounds__(256) split_kernel(const float4* __restrict__ src,
                                                    int n4, int mode) {
    uint2* dh;
    uint2* dl;
    if (mode == 0)      { dh = (uint2*)g_Xh;  dl = (uint2*)g_Xl;  }
    else if (mode == 1) { dh = (uint2*)g_Wsh; dl = (uint2*)g_Wsl; }
    else                { dh = (uint2*)g_Whh; dl = (uint2*)g_Whl; }
    for (int i = blockIdx.x * 256 + threadIdx.x; i < n4; i += gridDim.x * 256) {
        float4 v = src[i];
        unsigned h0, l0, h1, l1;
        split_pair(v.x, v.y, h0, l0);
        split_pair(v.z, v.w, h1, l1);
        dh[i] = make_uint2(h0, h1);
        dl[i] = make_uint2(l0, l1);
    }
}

// ---------------------------------------------------------------------------
// Kernel 1: fused factor GEMMs, split-K (8-way).
//   blocks x in [0,32):  G1: F_s tile  = X_b[s0:+64, :] @ Whid^T  (A=[m][k], B=[n][k])
//   blocks x in [32,64): G2: F_h^T tile = Wseq @ X_b[:, h0:+64]   (A=[m][k], B=[k][n] -> trans)
// blockIdx.y = ksplit: K range [ky*256, ky*256+256). fp32 partials out.
// CTA tile 64x64, K chunk 64, 8 warps (warp 32x16).
// ---------------------------------------------------------------------------
#define FP 72  // smem pitch (shorts): 144B = 9*16B -> conflict-free ldmatrix

__global__ void __launch_bounds__(256) fact_kernel() {
    __shared__ unsigned short Ah[64 * FP], Al[64 * FP], Bh[64 * FP], Bl[64 * FP];

    const int b = blockIdx.z, tid = threadIdx.x;
    const int ky = blockIdx.y;
    const int kbase = ky * KPER;
    const bool isG1 = (blockIdx.x < 32);
    const int tile = isG1 ? blockIdx.x : blockIdx.x - 32;

    // staging map: row = tid&63, kg8 = 8*(tid>>6); each thread: 16B at kg8 and kg8+32
    const int row = tid & 63, kg8 = (tid >> 6) * 8;

    const unsigned short *pAh, *pAl, *pBh, *pBl;
    long sB;
    if (isG1) {
        long aoff = ((long)(b * SS + tile * 64 + row)) * HH + kbase + kg8;
        pAh = g_Xh + aoff;  pAl = g_Xl + aoff;
        long boff = (long)row * HH + kbase + kg8;
        pBh = g_Whh + boff; pBl = g_Whl + boff;
        sB = 64;
    } else {
        long aoff = (long)row * SS + kbase + kg8;
        pAh = g_Wsh + aoff; pAl = g_Wsl + aoff;
        long boff = ((long)(b * SS + kbase + row)) * HH + tile * 64 + kg8;
        pBh = g_Xh + boff;  pBl = g_Xl + boff;
        sB = (long)64 * HH;
    }

    // prefetch chunk 0
    uint4 rah0 = *(const uint4*)pAh, rah1 = *(const uint4*)(pAh + 32);
    uint4 ral0 = *(const uint4*)pAl, ral1 = *(const uint4*)(pAl + 32);
    uint4 rbh0 = *(const uint4*)pBh, rbh1 = *(const uint4*)(pBh + 32);
    uint4 rbl0 = *(const uint4*)pBl, rbl1 = *(const uint4*)(pBl + 32);

    const int warpId = tid >> 5, lane = tid & 31;
    const int mB = (warpId >> 2) * 32, nB = (warpId & 3) * 16;

    const unsigned sAh = (unsigned)__cvta_generic_to_shared(Ah);
    const unsigned sAl = (unsigned)__cvta_generic_to_shared(Al);
    const unsigned sBh = (unsigned)__cvta_generic_to_shared(Bh);
    const unsigned sBl = (unsigned)__cvta_generic_to_shared(Bl);

    const unsigned aoffA = 2 * ((mB + (lane & 15)) * FP + (lane >> 4) * 8);
    const unsigned aAddrH = sAh + aoffA, aAddrL = sAl + aoffA;
    unsigned bAddrH, bAddrL;
    if (isG1) {  // B layout [n][k]
        const unsigned off = 2 * ((nB + (lane & 7) + ((lane & 16) >> 1)) * FP + (lane & 8));
        bAddrH = sBh + off; bAddrL = sBl + off;
    } else {     // B layout [k][n], read via ldmatrix.trans
        const unsigned off = 2 * ((lane & 15) * FP + nB + (lane >> 4) * 8);
        bAddrH = sBh + off; bAddrL = sBl + off;
    }

    float acc[2][2][4];
#pragma unroll
    for (int i = 0; i < 2; ++i)
#pragma unroll
        for (int j = 0; j < 2; ++j)
#pragma unroll
            for (int t = 0; t < 4; ++t) acc[i][j][t] = 0.0f;

#pragma unroll 1
    for (int kc = 0; kc < KPER / 64; ++kc) {
        // stage prefetched chunk
        *(uint4*)&Ah[row * FP + kg8]      = rah0;
        *(uint4*)&Ah[row * FP + kg8 + 32] = rah1;
        *(uint4*)&Al[row * FP + kg8]      = ral0;
        *(uint4*)&Al[row * FP + kg8 + 32] = ral1;
        *(uint4*)&Bh[row * FP + kg8]      = rbh0;
        *(uint4*)&Bh[row * FP + kg8 + 32] = rbh1;
        *(uint4*)&Bl[row * FP + kg8]      = rbl0;
        *(uint4*)&Bl[row * FP + kg8 + 32] = rbl1;
        __syncthreads();

        if (kc < KPER / 64 - 1) {
            pAh += 64; pAl += 64; pBh += sB; pBl += sB;
            rah0 = *(const uint4*)pAh; rah1 = *(const uint4*)(pAh + 32);
            ral0 = *(const uint4*)pAl; ral1 = *(const uint4*)(pAl + 32);
            rbh0 = *(const uint4*)pBh; rbh1 = *(const uint4*)(pBh + 32);
            rbl0 = *(const uint4*)pBl; rbl1 = *(const uint4*)(pBl + 32);
        }

#pragma unroll
        for (int kb = 0; kb < 64; kb += 16) {
            unsigned ah[2][4], al[2][4], bhf[4], blf[4];
            ldsm4(ah[0], aAddrH + kb * 2);
            ldsm4(ah[1], aAddrH + kb * 2 + 16 * FP * 2);
            ldsm4(al[0], aAddrL + kb * 2);
            ldsm4(al[1], aAddrL + kb * 2 + 16 * FP * 2);
            if (isG1) {
                ldsm4(bhf, bAddrH + kb * 2);
                ldsm4(blf, bAddrL + kb * 2);
            } else {
                ldsm4t(bhf, bAddrH + kb * (FP * 2));
                ldsm4t(blf, bAddrL + kb * (FP * 2));
            }
#pragma unroll
            for (int i = 0; i < 2; ++i)
#pragma unroll
                for (int j = 0; j < 2; ++j) {
                    mma_bf16(acc[i][j], ah[i], &bhf[2 * j]);
                    mma_bf16(acc[i][j], ah[i], &blf[2 * j]);
                    mma_bf16(acc[i][j], al[i], &bhf[2 * j]);
                }
        }
        __syncthreads();
    }

    // epilogue: fp32 partial tile -> g_part[gb][tile][ky][64*64]
    const int g = lane >> 2, q = lane & 3;
    const int gb = b * 2 + (isG1 ? 0 : 1);
    float* P = g_part + (((long)(gb * 32 + tile) * KSPLIT + ky) << 12);
#pragma unroll
    for (int i = 0; i < 2; ++i)
#pragma unroll
        for (int j = 0; j < 2; ++j) {
            int r0 = mB + i * 16 + g;
            int c  = nB + j * 8 + 2 * q;
            *(float2*)&P[r0 * 64 + c]       = make_float2(acc[i][j][0], acc[i][j][1]);
            *(float2*)&P[(r0 + 8) * 64 + c] = make_float2(acc[i][j][2], acc[i][j][3]);
        }
}

// ---------------------------------------------------------------------------
// Kernel 1b: reduce 8 split-K partials, split fp32 -> hi/lo bf16 factors.
// One thread = 4 consecutive n of one (gb, tile, m) row.
// ---------------------------------------------------------------------------
__global__ void __launch_bounds__(256) reduce_kernel() {
    const int t  = blockIdx.x * 256 + threadIdx.x;   // 0 .. 262143
    const int t4 = t << 2;
    const int n    = t4 & 63;
    const int m    = (t4 >> 6) & 63;
    const int tile = (t4 >> 12) & 31;
    const int gb   = t4 >> 17;            // 0..7: b*2 + gemm
    const int b    = gb >> 1;
    const int gemm = gb & 1;              // 0 = F_s, 1 = F_h^T

    const float4* P = (const float4*)g_part +
                      ((long)(gb * 32 + tile) * KSPLIT * 1024 + ((m * 64 + n) >> 2));
    float4 s = P[0];
#pragma unroll
    for (int k = 1; k < KSPLIT; ++k) {
        float4 v = P[k * 1024];
        s.x += v.x; s.y += v.y; s.z += v.z; s.w += v.w;
    }

    unsigned h0, l0, h1, l1;
    split_pair(s.x, s.y, h0, l0);
    split_pair(s.z, s.w, h1, l1);

    long base;
    unsigned short *oh, *ol;
    if (gemm == 0) {
        base = ((long)(b * SS + tile * 64 + m)) * RR + n;
        oh = g_Fsh; ol = g_Fsl;
    } else {
        base = ((long)(b * RR + m)) * HH + tile * 64 + n;
        oh = g_Fhh; ol = g_Fhl;
    }
    *(uint2*)&oh[base] = make_uint2(h0, h1);
    *(uint2*)&ol[base] = make_uint2(l0, l1);
}

// ---------------------------------------------------------------------------
// Kernel 2: Out_b = F_s[b] (S x 64) @ F_h^T[b] (64 x H), fp32 out.
// CTA tile 128x128, K=64 resident, 8 warps (warp 64x32), dynamic smem.
// ---------------------------------------------------------------------------
#define OAP 72    // A pitch (shorts)
#define OBP 136   // B pitch (shorts): 272B = 17*16B -> conflict-free trans ldmatrix
#define OSM_AL (128 * OAP)
#define OSM_BH (2 * 128 * OAP)
#define OSM_BL (2 * 128 * OAP + 64 * OBP)
#define OSM_TOT_BYTES ((2 * 128 * OAP + 2 * 64 * OBP) * 2)  // 71680

__global__ void __launch_bounds__(256) out_kernel(float* __restrict__ Out) {
    extern __shared__ unsigned short sm[];
    unsigned short* Ah = sm;
    unsigned short* Al = sm + OSM_AL;
    unsigned short* Bh = sm + OSM_BH;
    unsigned short* Bl = sm + OSM_BL;

    const int b = blockIdx.z, s0 = blockIdx.y * 128, h0 = blockIdx.x * 128;
    const int tid = threadIdx.x;

    {
        const unsigned short* gh = g_Fsh + ((long)(b * SS + s0)) * RR;
        const unsigned short* gl = g_Fsl + ((long)(b * SS + s0)) * RR;
#pragma unroll
        for (int p = 0; p < 4; ++p) {
            int idx = tid + p * 256;
            int r = idx >> 3, c = (idx & 7) * 8;
            *(uint4*)&Ah[r * OAP + c] = *(const uint4*)&gh[r * RR + c];
            *(uint4*)&Al[r * OAP + c] = *(const uint4*)&gl[r * RR + c];
        }
        const unsigned short* bhg = g_Fhh + (long)b * RR * HH + h0;
        const unsigned short* blg = g_Fhl + (long)b * RR * HH + h0;
#pragma unroll
        for (int p = 0; p < 4; ++p) {
            int idx = tid + p * 256;
            int r = idx >> 4, c = (idx & 15) * 8;
            *(uint4*)&Bh[r * OBP + c] = *(const uint4*)&bhg[(long)r * HH + c];
            *(uint4*)&Bl[r * OBP + c] = *(const uint4*)&blg[(long)r * HH + c];
        }
    }
    __syncthreads();

    const int warpId = tid >> 5, lane = tid & 31;
    const int mB = (warpId >> 2) * 64, nB = (warpId & 3) * 32;

    const unsigned sAh = (unsigned)__cvta_generic_to_shared(Ah);
    const unsigned sAl = (unsigned)__cvta_generic_to_shared(Al);
    const unsigned sBh = (unsigned)__cvta_generic_to_shared(Bh);
    const unsigned sBl = (unsigned)__cvta_generic_to_shared(Bl);

    const unsigned aoff = 2 * ((mB + (lane & 15)) * OAP + (lane >> 4) * 8);
    const unsigned aH = sAh + aoff, aL = sAl + aoff;
    const unsigned boff = 2 * ((lane & 15) * OBP + nB + (lane >> 4) * 8);
    const unsigned bH = sBh + boff, bL = sBl + boff;

    float acc[4][4][4];
#pragma unroll
    for (int i = 0; i < 4; ++i)
#pragma unroll
        for (int j = 0; j < 4; ++j)
#pragma unroll
            for (int t = 0; t < 4; ++t) acc[i][j][t] = 0.0f;

#pragma unroll
    for (int kb = 0; kb < 64; kb += 16) {
        unsigned bhf[2][4], blf[2][4];
        ldsm4t(bhf[0], bH + kb * (OBP * 2));
        ldsm4t(bhf[1], bH + kb * (OBP * 2) + 16 * 2);
        ldsm4t(blf[0], bL + kb * (OBP * 2));
        ldsm4t(blf[1], bL + kb * (OBP * 2) + 16 * 2);
#pragma unroll
        for (int i = 0; i < 4; ++i) {
            unsigned ah[4], al[4];
            ldsm4(ah, aH + kb * 2 + i * (16 * OAP * 2));
            ldsm4(al, aL + kb * 2 + i * (16 * OAP * 2));
#pragma unroll
            for (int j = 0; j < 4; ++j) {
                const unsigned* bhp = &bhf[j >> 1][(j & 1) * 2];
                const unsigned* blp = &blf[j >> 1][(j & 1) * 2];
                mma_bf16(acc[i][j], ah, bhp);
                mma_bf16(acc[i][j], ah, blp);
                mma_bf16(acc[i][j], al, bhp);
            }
        }
    }

    const int g = lane >> 2, q = lane & 3;
    float* O = Out + ((long)(b * SS + s0)) * HH + h0;
#pragma unroll
    for (int i = 0; i < 4; ++i)
#pragma unroll
        for (int j = 0; j < 4; ++j) {
            int r = mB + i * 16 + g;
            int c = nB + j * 8 + 2 * q;
            *(float2*)&O[(long)r * HH + c]       = make_float2(acc[i][j][0], acc[i][j][1]);
            *(float2*)&O[(long)(r + 8) * HH + c] = make_float2(acc[i][j][2], acc[i][j][3]);
        }
}

// ---------------------------------------------------------------------------
// Launch: inputs per metadata: hidden_states, grid_chw (unused), W_seq, W_hid
// ---------------------------------------------------------------------------
extern "C" void kernel_launch(void* const* d_in, const int* in_sizes, int n_in,
                              void* d_out, int out_size) {
    const float* X    = (const float*)d_in[0];
    const float* Wseq = (const float*)d_in[2];
    const float* Whid = (const float*)d_in[3];
    float* Out = (float*)d_out;

    cudaFuncSetAttribute(out_kernel, cudaFuncAttributeMaxDynamicSharedMemorySize,
                         OSM_TOT_BYTES);

    split_kernel<<<4096, 256>>>((const float4*)X,    BB * SS * HH / 4, 0);
    split_kernel<<<128,  256>>>((const float4*)Wseq, RR * SS / 4,      1);
    split_kernel<<<128,  256>>>((const float4*)Whid, RR * HH / 4,      2);
    fact_kernel<<<dim3(64, KSPLIT, BB), 256>>>();
    reduce_kernel<<<1024, 256>>>();
    out_kernel<<<dim3(HH / 128, SS / 128, BB), 256, OSM_TOT_BYTES>>>(Out);
}

// round 7
// speedup vs baseline: 1.9437x; 1.5641x over previous
#include <cuda_runtime.h>
#include <cuda_bf16.h>

#define BB 4
#define SS 2048
#define HH 2048
#define RR 64
#define KSPLIT 8
#define KPER (2048 / KSPLIT)   // 256 per CTA
#define NC (KPER / 32)         // 8 k-chunks of 32

// ---------------------------------------------------------------------------
// Global scratch (static device arrays; no runtime allocation).
// ---------------------------------------------------------------------------
__device__ __align__(16) unsigned short g_Xh[BB * SS * HH];
__device__ __align__(16) unsigned short g_Xl[BB * SS * HH];
__device__ __align__(16) unsigned short g_Wsh[RR * SS];
__device__ __align__(16) unsigned short g_Wsl[RR * SS];
__device__ __align__(16) unsigned short g_Whh[RR * HH];
__device__ __align__(16) unsigned short g_Whl[RR * HH];
__device__ __align__(16) unsigned short g_Fsh[BB * SS * RR];  // F_s [b][s][r]
__device__ __align__(16) unsigned short g_Fsl[BB * SS * RR];
__device__ __align__(16) unsigned short g_Fhh[BB * HH * RR];  // F_h [b][h][r]
__device__ __align__(16) unsigned short g_Fhl[BB * HH * RR];
// split-K fp32 partials: [gb(8)][tile(16)][ky(8)][128*64]
__device__ __align__(16) float g_part[8 * 16 * KSPLIT * 128 * 64];

// ---------------------------------------------------------------------------
// Helpers
// ---------------------------------------------------------------------------
__device__ __forceinline__ unsigned pack2(float v0, float v1) {
    __nv_bfloat162 t = __floats2bfloat162_rn(v0, v1);
    return *reinterpret_cast<unsigned*>(&t);
}

__device__ __forceinline__ void split_pair(float v0, float v1, unsigned& h, unsigned& l) {
    h = pack2(v0, v1);
    float h0 = __uint_as_float(h << 16);
    float h1 = __uint_as_float(h & 0xFFFF0000u);
    l = pack2(v0 - h0, v1 - h1);
}

__device__ __forceinline__ void mma_bf16(float c[4], const unsigned a[4], const unsigned b[2]) {
    asm volatile(
        "mma.sync.aligned.m16n8k16.row.col.f32.bf16.bf16.f32 "
        "{%0,%1,%2,%3}, {%4,%5,%6,%7}, {%8,%9}, {%0,%1,%2,%3};\n"
        : "+f"(c[0]), "+f"(c[1]), "+f"(c[2]), "+f"(c[3])
        : "r"(a[0]), "r"(a[1]), "r"(a[2]), "r"(a[3]), "r"(b[0]), "r"(b[1]));
}

__device__ __forceinline__ void ldsm4(unsigned* r, unsigned a) {
    asm volatile("ldmatrix.sync.aligned.m8n8.x4.shared.b16 {%0,%1,%2,%3}, [%4];\n"
                 : "=r"(r[0]), "=r"(r[1]), "=r"(r[2]), "=r"(r[3]) : "r"(a));
}
__device__ __forceinline__ void ldsm4t(unsigned* r, unsigned a) {
    asm volatile("ldmatrix.sync.aligned.m8n8.x4.trans.shared.b16 {%0,%1,%2,%3}, [%4];\n"
                 : "=r"(r[0]), "=r"(r[1]), "=r"(r[2]), "=r"(r[3]) : "r"(a));
}

__device__ __forceinline__ void cp16(unsigned dst, const void* src) {
    asm volatile("cp.async.cg.shared.global [%0], [%1], 16;\n" :: "r"(dst), "l"(src));
}
__device__ __forceinline__ void cp_commit() { asm volatile("cp.async.commit_group;\n"); }
__device__ __forceinline__ void cp_wait1()  { asm volatile("cp.async.wait_group 1;\n" ::: "memory"); }
__device__ __forceinline__ void cp_wait0()  { asm volatile("cp.async.wait_group 0;\n" ::: "memory"); }

// ---------------------------------------------------------------------------
// Kernel 0: split fp32 tensor -> hi/lo bf16 scratch. mode: 0=X, 1=Wseq, 2=Whid
// ---------------------------------------------------------------------------
__global__ void __launch_bounds__(256) split_kernel(const float4* __restrict__ src,
                                                    int n4, int mode) {
    uint2* dh;
    uint2* dl;
    if (mode == 0)      { dh = (uint2*)g_Xh;  dl = (uint2*)g_Xl;  }
    else if (mode == 1) { dh = (uint2*)g_Wsh; dl = (uint2*)g_Wsl; }
    else                { dh = (uint2*)g_Whh; dl = (uint2*)g_Whl; }
    for (int i = blockIdx.x * 256 + threadIdx.x; i < n4; i += gridDim.x * 256) {
        float4 v = src[i];
        unsigned h0, l0, h1, l1;
        split_pair(v.x, v.y, h0, l0);
        split_pair(v.z, v.w, h1, l1);
        dh[i] = make_uint2(h0, h1);
        dl[i] = make_uint2(l0, l1);
    }
}

// ---------------------------------------------------------------------------
// Kernel 1: fused factor GEMMs, split-K, cp.async 2-stage pipeline.
//   x in [0,16):  G1: F_s rows  = X_b[m0:+128, :] @ Whid^T      A=[m][k] (ldsm)
//   x in [16,32): G2: F_h rows  = (X_b[:, h0:+128])^T @ Wseq^T  A=[k][m] (ldsm.trans)
// Both: M tile 128, N=64, K chunk 32. 8 warps, warp tile 32x32.
// ---------------------------------------------------------------------------
#define AP1 40     // G1 A pitch (shorts) for [m=128][k=32]
#define AP2 136    // G2 A pitch (shorts) for [k=32][m=128]
#define BP  40     // B pitch for [n=64][k=32]
#define ABUF 5120                        // shorts per A sub-buffer (max of both layouts)
#define BBUF 2560                        // shorts per B sub-buffer
#define STG  (2 * ABUF + 2 * BBUF)       // 15360 shorts per stage
#define FSM_BYTES (2 * STG * 2)          // 61440 bytes (2 stages)

__global__ void __launch_bounds__(256) fact_kernel() {
    extern __shared__ unsigned short fsm[];
    const unsigned sbase = (unsigned)__cvta_generic_to_shared(fsm);

    const int b = blockIdx.z, ky = blockIdx.y, tid = threadIdx.x;
    const bool isG1 = (blockIdx.x < 16);
    const int tile = isG1 ? blockIdx.x : blockIdx.x - 16;
    const int m0 = tile * 128;
    const int kbase = ky * KPER;

    // ---- staging (cp.async), per stage: A 128x32 hi/lo, B 64x32 hi/lo ----
    auto issue = [&](int kc, int s) {
        const unsigned base = sbase + (unsigned)(s * STG * 2);
        const int k0 = kbase + kc * 32;
        if (isG1) {
#pragma unroll
            for (int p = 0; p < 2; ++p) {
                int idx = tid + p * 256;
                int row = idx >> 2, c = (idx & 3) * 8;
                long off = ((long)(b * SS + m0 + row)) * HH + k0 + c;
                unsigned d = base + (unsigned)((row * AP1 + c) * 2);
                cp16(d, g_Xh + off);
                cp16(d + ABUF * 2, g_Xl + off);
            }
            {
                int row = tid >> 2, c = (tid & 3) * 8;
                long off = (long)row * HH + k0 + c;
                unsigned d = base + (unsigned)((2 * ABUF + row * BP + c) * 2);
                cp16(d, g_Whh + off);
                cp16(d + BBUF * 2, g_Whl + off);
            }
        } else {
#pragma unroll
            for (int p = 0; p < 2; ++p) {
                int idx = tid + p * 256;
                int kr = idx >> 4, c = (idx & 15) * 8;
                long off = ((long)(b * SS + k0 + kr)) * HH + m0 + c;
                unsigned d = base + (unsigned)((kr * AP2 + c) * 2);
                cp16(d, g_Xh + off);
                cp16(d + ABUF * 2, g_Xl + off);
            }
            {
                int row = tid >> 2, c = (tid & 3) * 8;
                long off = (long)row * SS + k0 + c;
                unsigned d = base + (unsigned)((2 * ABUF + row * BP + c) * 2);
                cp16(d, g_Wsh + off);
                cp16(d + BBUF * 2, g_Wsl + off);
            }
        }
    };

    issue(0, 0); cp_commit();
    issue(1, 1); cp_commit();

    const int warpId = tid >> 5, lane = tid & 31;
    const int mB = (warpId >> 1) * 32, nB = (warpId & 1) * 32;

    // fragment lane offsets (bytes, relative to sub-buffer start)
    const unsigned aoff1 = (unsigned)(((mB + (lane & 15)) * AP1 + (lane >> 4) * 8) * 2);
    const unsigned aoff2 = (unsigned)(((((lane & 7) + ((lane & 16) >> 1)) * AP2) +
                                       mB + ((lane >> 3) & 1) * 8) * 2);
    const unsigned boff  = (unsigned)(((nB + (lane & 7) + ((lane & 16) >> 1)) * BP +
                                       (lane & 8)) * 2);

    float acc[2][4][4];
#pragma unroll
    for (int i = 0; i < 2; ++i)
#pragma unroll
        for (int j = 0; j < 4; ++j)
#pragma unroll
            for (int t = 0; t < 4; ++t) acc[i][j][t] = 0.0f;

#pragma unroll 1
    for (int kc = 0; kc < NC; ++kc) {
        if (kc < NC - 1) cp_wait1(); else cp_wait0();
        __syncthreads();

        const unsigned base = sbase + (unsigned)((kc & 1) * STG * 2);
        const unsigned bAh = base, bAl = base + ABUF * 2;
        const unsigned bBh = base + 2 * ABUF * 2, bBl = bBh + BBUF * 2;

#pragma unroll
        for (int kb = 0; kb < 32; kb += 16) {
            unsigned bhf[2][4], blf[2][4];
            ldsm4(bhf[0], bBh + boff + kb * 2);
            ldsm4(bhf[1], bBh + boff + kb * 2 + 16 * BP * 2);
            ldsm4(blf[0], bBl + boff + kb * 2);
            ldsm4(blf[1], bBl + boff + kb * 2 + 16 * BP * 2);
#pragma unroll
            for (int i = 0; i < 2; ++i) {
                unsigned ah[4], al[4];
                if (isG1) {
                    unsigned o = aoff1 + (unsigned)(i * 16 * AP1 * 2 + kb * 2);
                    ldsm4(ah, bAh + o);
                    ldsm4(al, bAl + o);
                } else {
                    unsigned o = aoff2 + (unsigned)(kb * AP2 * 2 + i * 16 * 2);
                    ldsm4t(ah, bAh + o);
                    ldsm4t(al, bAl + o);
                }
#pragma unroll
                for (int j = 0; j < 4; ++j) {
                    const unsigned* bhp = &bhf[j >> 1][(j & 1) * 2];
                    const unsigned* blp = &blf[j >> 1][(j & 1) * 2];
                    mma_bf16(acc[i][j], ah, bhp);
                    mma_bf16(acc[i][j], ah, blp);
                    mma_bf16(acc[i][j], al, bhp);
                }
            }
        }
        __syncthreads();
        if (kc + 2 < NC) { issue(kc + 2, kc & 1); cp_commit(); }
    }

    // epilogue: fp32 partial tile (128x64) -> g_part
    const int g = lane >> 2, q = lane & 3;
    const int gb = b * 2 + (isG1 ? 0 : 1);
    float* P = g_part + ((long)((gb * 16 + tile) * KSPLIT + ky)) * (128 * 64);
#pragma unroll
    for (int i = 0; i < 2; ++i)
#pragma unroll
        for (int j = 0; j < 4; ++j) {
            int r0 = mB + i * 16 + g;
            int c  = nB + j * 8 + 2 * q;
            *(float2*)&P[r0 * 64 + c]       = make_float2(acc[i][j][0], acc[i][j][1]);
            *(float2*)&P[(r0 + 8) * 64 + c] = make_float2(acc[i][j][2], acc[i][j][3]);
        }
}

// ---------------------------------------------------------------------------
// Kernel 1b: reduce split-K partials, split fp32 -> hi/lo bf16 factors.
// ---------------------------------------------------------------------------
__global__ void __launch_bounds__(256) reduce_kernel() {
    const int t  = blockIdx.x * 256 + threadIdx.x;   // 0 .. 262143
    const int t4 = t << 2;
    const int n    = t4 & 63;
    const int m    = (t4 >> 6) & 127;
    const int tile = (t4 >> 13) & 15;
    const int gb   = t4 >> 17;            // b*2 + gemm
    const int b    = gb >> 1;
    const int gemm = gb & 1;

    const float4* P = (const float4*)g_part +
                      ((long)(gb * 16 + tile) * KSPLIT * (128 * 64) + (m * 64 + n)) / 4;
    float4 s = P[0];
#pragma unroll
    for (int k = 1; k < KSPLIT; ++k) {
        float4 v = P[k * (128 * 64 / 4)];
        s.x += v.x; s.y += v.y; s.z += v.z; s.w += v.w;
    }

    unsigned h0, l0, h1, l1;
    split_pair(s.x, s.y, h0, l0);
    split_pair(s.z, s.w, h1, l1);

    const long base = ((long)b * SS + tile * 128 + m) * RR + n;  // SS == HH
    unsigned short* oh = gemm == 0 ? g_Fsh : g_Fhh;
    unsigned short* ol = gemm == 0 ? g_Fsl : g_Fhl;
    *(uint2*)&oh[base] = make_uint2(h0, h1);
    *(uint2*)&ol[base] = make_uint2(l0, l1);
}

// ---------------------------------------------------------------------------
// Kernel 2: Out_b = F_s[b] (S x 64) @ F_h[b]^T (64 x H), fp32 out.
// CTA 128x128, K=64 resident, 8 warps (warp 64x32). Both operands [rows][k=64].
// ---------------------------------------------------------------------------
#define OAP 72
#define OSM_AL (128 * OAP)
#define OSM_BH (2 * 128 * OAP)
#define OSM_BL (3 * 128 * OAP)
#define OSM_TOT_BYTES (4 * 128 * OAP * 2)  // 73728

__global__ void __launch_bounds__(256) out_kernel(float* __restrict__ Out) {
    extern __shared__ unsigned short sm[];
    unsigned short* Ah = sm;
    unsigned short* Al = sm + OSM_AL;
    unsigned short* Bh = sm + OSM_BH;
    unsigned short* Bl = sm + OSM_BL;

    const int b = blockIdx.z, s0 = blockIdx.y * 128, h0 = blockIdx.x * 128;
    const int tid = threadIdx.x;

    {
        const unsigned short* agh = g_Fsh + ((long)(b * SS + s0)) * RR;
        const unsigned short* agl = g_Fsl + ((long)(b * SS + s0)) * RR;
        const unsigned short* bgh = g_Fhh + ((long)(b * HH + h0)) * RR;
        const unsigned short* bgl = g_Fhl + ((long)(b * HH + h0)) * RR;
#pragma unroll
        for (int p = 0; p < 4; ++p) {
            int idx = tid + p * 256;
            int r = idx >> 3, c = (idx & 7) * 8;
            *(uint4*)&Ah[r * OAP + c] = *(const uint4*)&agh[r * RR + c];
            *(uint4*)&Al[r * OAP + c] = *(const uint4*)&agl[r * RR + c];
            *(uint4*)&Bh[r * OAP + c] = *(const uint4*)&bgh[r * RR + c];
            *(uint4*)&Bl[r * OAP + c] = *(const uint4*)&bgl[r * RR + c];
        }
    }
    __syncthreads();

    const int warpId = tid >> 5, lane = tid & 31;
    const int mB = (warpId >> 2) * 64, nB = (warpId & 3) * 32;

    const unsigned sAh = (unsigned)__cvta_generic_to_shared(Ah);
    const unsigned sAl = (unsigned)__cvta_generic_to_shared(Al);
    const unsigned sBh = (unsigned)__cvta_generic_to_shared(Bh);
    const unsigned sBl = (unsigned)__cvta_generic_to_shared(Bl);

    const unsigned aoff = 2 * ((mB + (lane & 15)) * OAP + (lane >> 4) * 8);
    const unsigned aH = sAh + aoff, aL = sAl + aoff;
    const unsigned boff = 2 * ((nB + (lane & 7) + ((lane & 16) >> 1)) * OAP + (lane & 8));
    const unsigned bH = sBh + boff, bL = sBl + boff;

    float acc[4][4][4];
#pragma unroll
    for (int i = 0; i < 4; ++i)
#pragma unroll
        for (int j = 0; j < 4; ++j)
#pragma unroll
            for (int t = 0; t < 4; ++t) acc[i][j][t] = 0.0f;

#pragma unroll
    for (int kb = 0; kb < 64; kb += 16) {
        unsigned bhf[2][4], blf[2][4];
        ldsm4(bhf[0], bH + kb * 2);
        ldsm4(bhf[1], bH + kb * 2 + 16 * OAP * 2);
        ldsm4(blf[0], bL + kb * 2);
        ldsm4(blf[1], bL + kb * 2 + 16 * OAP * 2);
#pragma unroll
        for (int i = 0; i < 4; ++i) {
            unsigned ah[4], al[4];
            ldsm4(ah, aH + kb * 2 + i * (16 * OAP * 2));
            ldsm4(al, aL + kb * 2 + i * (16 * OAP * 2));
#pragma unroll
            for (int j = 0; j < 4; ++j) {
                const unsigned* bhp = &bhf[j >> 1][(j & 1) * 2];
                const unsigned* blp = &blf[j >> 1][(j & 1) * 2];
                mma_bf16(acc[i][j], ah, bhp);
                mma_bf16(acc[i][j], ah, blp);
                mma_bf16(acc[i][j], al, bhp);
            }
        }
    }

    const int g = lane >> 2, q = lane & 3;
    float* O = Out + ((long)(b * SS + s0)) * HH + h0;
#pragma unroll
    for (int i = 0; i < 4; ++i)
#pragma unroll
        for (int j = 0; j < 4; ++j) {
            int r = mB + i * 16 + g;
            int c = nB + j * 8 + 2 * q;
            *(float2*)&O[(long)r * HH + c]       = make_float2(acc[i][j][0], acc[i][j][1]);
            *(float2*)&O[(long)(r + 8) * HH + c] = make_float2(acc[i][j][2], acc[i][j][3]);
        }
}

// ---------------------------------------------------------------------------
// Launch: inputs per metadata: hidden_states, grid_chw (unused), W_seq, W_hid
// ---------------------------------------------------------------------------
extern "C" void kernel_launch(void* const* d_in, const int* in_sizes, int n_in,
                              void* d_out, int out_size) {
    const float* X    = (const float*)d_in[0];
    const float* Wseq = (const float*)d_in[2];
    const float* Whid = (const float*)d_in[3];
    float* Out = (float*)d_out;

    cudaFuncSetAttribute(fact_kernel, cudaFuncAttributeMaxDynamicSharedMemorySize,
                         FSM_BYTES);
    cudaFuncSetAttribute(out_kernel, cudaFuncAttributeMaxDynamicSharedMemorySize,
                         OSM_TOT_BYTES);

    split_kernel<<<4096, 256>>>((const float4*)X,    BB * SS * HH / 4, 0);
    split_kernel<<<128,  256>>>((const float4*)Wseq, RR * SS / 4,      1);
    split_kernel<<<128,  256>>>((const float4*)Whid, RR * HH / 4,      2);
    fact_kernel<<<dim3(32, KSPLIT, BB), 256, FSM_BYTES>>>();
    reduce_kernel<<<1024, 256>>>();
    out_kernel<<<dim3(HH / 128, SS / 128, BB), 256, OSM_TOT_BYTES>>>(Out);
}

// round 8
// speedup vs baseline: 2.4520x; 1.2615x over previous
#include <cuda_runtime.h>
#include <cuda_bf16.h>

#define BB 4
#define SS 2048
#define HH 2048
#define RR 64
#define KSPLIT 4
#define KPER (2048 / KSPLIT)   // 512 per CTA
#define NC (KPER / 32)         // 16 k-chunks of 32

// ---------------------------------------------------------------------------
// Global scratch (static device arrays; no runtime allocation).
// ---------------------------------------------------------------------------
__device__ __align__(16) unsigned short g_Wsh[RR * SS];
__device__ __align__(16) unsigned short g_Wsl[RR * SS];
__device__ __align__(16) unsigned short g_Whh[RR * HH];
__device__ __align__(16) unsigned short g_Whl[RR * HH];
__device__ __align__(16) unsigned short g_Fsh[BB * SS * RR];  // F_s [b][s][r]
__device__ __align__(16) unsigned short g_Fsl[BB * SS * RR];
__device__ __align__(16) unsigned short g_Fhh[BB * HH * RR];  // F_h [b][h][r]
__device__ __align__(16) unsigned short g_Fhl[BB * HH * RR];
// split-K fp32 partials: [gb(8)][tile(16)][ky(4)][128*64]  (16.8 MB)
__device__ __align__(16) float g_part[8 * 16 * KSPLIT * 128 * 64];

// ---------------------------------------------------------------------------
// Helpers
// ---------------------------------------------------------------------------
__device__ __forceinline__ unsigned pack2(float v0, float v1) {
    __nv_bfloat162 t = __floats2bfloat162_rn(v0, v1);
    return *reinterpret_cast<unsigned*>(&t);
}

__device__ __forceinline__ void split_pair(float v0, float v1, unsigned& h, unsigned& l) {
    h = pack2(v0, v1);
    float h0 = __uint_as_float(h << 16);
    float h1 = __uint_as_float(h & 0xFFFF0000u);
    l = pack2(v0 - h0, v1 - h1);
}

__device__ __forceinline__ void mma_bf16(float c[4], const unsigned a[4], const unsigned b[2]) {
    asm volatile(
        "mma.sync.aligned.m16n8k16.row.col.f32.bf16.bf16.f32 "
        "{%0,%1,%2,%3}, {%4,%5,%6,%7}, {%8,%9}, {%0,%1,%2,%3};\n"
        : "+f"(c[0]), "+f"(c[1]), "+f"(c[2]), "+f"(c[3])
        : "r"(a[0]), "r"(a[1]), "r"(a[2]), "r"(a[3]), "r"(b[0]), "r"(b[1]));
}

__device__ __forceinline__ void ldsm4(unsigned* r, unsigned a) {
    asm volatile("ldmatrix.sync.aligned.m8n8.x4.shared.b16 {%0,%1,%2,%3}, [%4];\n"
                 : "=r"(r[0]), "=r"(r[1]), "=r"(r[2]), "=r"(r[3]) : "r"(a));
}
__device__ __forceinline__ void ldsm4t(unsigned* r, unsigned a) {
    asm volatile("ldmatrix.sync.aligned.m8n8.x4.trans.shared.b16 {%0,%1,%2,%3}, [%4];\n"
                 : "=r"(r[0]), "=r"(r[1]), "=r"(r[2]), "=r"(r[3]) : "r"(a));
}

__device__ __forceinline__ void cp16(unsigned dst, const void* src) {
    asm volatile("cp.async.cg.shared.global [%0], [%1], 16;\n" :: "r"(dst), "l"(src));
}
__device__ __forceinline__ void cp_commit() { asm volatile("cp.async.commit_group;\n"); }
__device__ __forceinline__ void cp_wait0()  { asm volatile("cp.async.wait_group 0;\n" ::: "memory"); }

// ---------------------------------------------------------------------------
// Kernel 0: split the two small W matrices fp32 -> hi/lo bf16.
// blocks [0,64): Wseq, [64,128): Whid. Each RR*2048 floats.
// ---------------------------------------------------------------------------
__global__ void __launch_bounds__(256) wsplit_kernel(const float4* __restrict__ Wseq,
                                                     const float4* __restrict__ Whid) {
    const bool second = blockIdx.x >= 64;
    const float4* src = second ? Whid : Wseq;
    uint2* dh = (uint2*)(second ? g_Whh : g_Wsh);
    uint2* dl = (uint2*)(second ? g_Whl : g_Wsl);
    const int n4 = RR * SS / 4;
    for (int i = (blockIdx.x & 63) * 256 + threadIdx.x; i < n4; i += 64 * 256) {
        float4 v = src[i];
        unsigned h0, l0, h1, l1;
        split_pair(v.x, v.y, h0, l0);
        split_pair(v.z, v.w, h1, l1);
        dh[i] = make_uint2(h0, h1);
        dl[i] = make_uint2(l0, l1);
    }
}

// ---------------------------------------------------------------------------
// Kernel 1: fused factor GEMMs, split-K, fused fp32->bf16 split of X.
//   x in [0,16):  G1: F_s rows = X_b[m0:+128, :] @ Whid^T      A=[m][k] (ldsm)
//   x in [16,32): G2: F_h rows = (X_b[:, h0:+128])^T @ Wseq^T  A=[k][m] (ldsm.trans)
// A: LDG.128 fp32 X -> register split -> STS bf16 hi/lo (double-buffered smem).
// B: pre-split W via cp.async. One __syncthreads per k-chunk.
// M tile 128, N=64, K chunk 32. 8 warps, warp tile 32x32.
// ---------------------------------------------------------------------------
#define AP1 40     // G1 A pitch (shorts): [m=128][k=32]
#define AP2 136    // G2 A pitch (shorts): [k=32][m=128]
#define BP  40     // B pitch: [n=64][k=32]
#define ABUF 5120                        // shorts per A sub-buffer
#define BBUF 2560                        // shorts per B sub-buffer
#define STG  (2 * ABUF + 2 * BBUF)       // 15360 shorts per stage
#define FSM_BYTES (2 * STG * 2)          // 61440 bytes (2 stages)

__global__ void __launch_bounds__(256, 2) fact_kernel(const float* __restrict__ X) {
    extern __shared__ unsigned short fsm[];
    const unsigned sbase = (unsigned)__cvta_generic_to_shared(fsm);

    const int b = blockIdx.z, ky = blockIdx.y, tid = threadIdx.x;
    const bool isG1 = (blockIdx.x < 16);
    const int tile = isG1 ? blockIdx.x : blockIdx.x - 16;
    const int m0 = tile * 128;
    const int kbase = ky * KPER;

    // ---- A source pointers (fp32 X), 4 x float4 per thread per chunk ----
    const float* pA[4];
    long astep;
    int sr[4], sc[4];  // smem (row, col) per p
    if (isG1) {
#pragma unroll
        for (int p = 0; p < 4; ++p) {
            int idx = tid + p * 256;
            int row = idx >> 3, c4 = (idx & 7) * 4;
            pA[p] = X + ((long)(b * SS + m0 + row)) * HH + kbase + c4;
            sr[p] = row; sc[p] = c4;
        }
        astep = 32;
    } else {
#pragma unroll
        for (int p = 0; p < 4; ++p) {
            int idx = tid + p * 256;
            int kr = idx >> 5, c4 = (idx & 31) * 4;
            pA[p] = X + ((long)(b * SS + kbase + kr)) * HH + m0 + c4;
            sr[p] = kr; sc[p] = c4;
        }
        astep = (long)32 * HH;
    }
    const int APx = isG1 ? AP1 : AP2;

    // ---- B staging (cp.async): 64 n-rows x 32 k, hi+lo ----
    const unsigned short* Bh_src = isG1 ? g_Whh : g_Wsh;
    const unsigned short* Bl_src = isG1 ? g_Whl : g_Wsl;
    const int brow = tid >> 2, bc = (tid & 3) * 8;
    const long bsoff = (long)brow * (isG1 ? HH : SS) + kbase + bc;
    const unsigned bdst = (unsigned)((2 * ABUF + brow * BP + bc) * 2);

    auto issueB = [&](int kc, int s) {
        const unsigned base = sbase + (unsigned)(s * STG * 2) + bdst;
        const long off = bsoff + kc * 32;
        cp16(base, Bh_src + off);
        cp16(base + BBUF * 2, Bl_src + off);
    };

    float4 pa[4];
#pragma unroll
    for (int p = 0; p < 4; ++p) pa[p] = *(const float4*)pA[p];
    issueB(0, 0); cp_commit();

    const int warpId = tid >> 5, lane = tid & 31;
    const int mB = (warpId >> 1) * 32, nB = (warpId & 1) * 32;

    const unsigned aoff1 = (unsigned)(((mB + (lane & 15)) * AP1 + (lane >> 4) * 8) * 2);
    const unsigned aoff2 = (unsigned)(((((lane & 7) + ((lane & 16) >> 1)) * AP2) +
                                       mB + ((lane >> 3) & 1) * 8) * 2);
    const unsigned boff  = (unsigned)(((nB + (lane & 7) + ((lane & 16) >> 1)) * BP +
                                       (lane & 8)) * 2);

    float acc[2][4][4];
#pragma unroll
    for (int i = 0; i < 2; ++i)
#pragma unroll
        for (int j = 0; j < 4; ++j)
#pragma unroll
            for (int t = 0; t < 4; ++t) acc[i][j][t] = 0.0f;

#pragma unroll 1
    for (int kc = 0; kc < NC; ++kc) {
        const unsigned base = sbase + (unsigned)((kc & 1) * STG * 2);
        const unsigned bAh = base, bAl = base + ABUF * 2;
        const unsigned bBh = base + 2 * ABUF * 2, bBl = bBh + BBUF * 2;

        // split prefetched A regs -> smem stage kc&1 (readers drained 2 syncs ago)
        unsigned short* Ahp = fsm + (kc & 1) * STG;
        unsigned short* Alp = Ahp + ABUF;
#pragma unroll
        for (int p = 0; p < 4; ++p) {
            unsigned h0, l0, h1, l1;
            split_pair(pa[p].x, pa[p].y, h0, l0);
            split_pair(pa[p].z, pa[p].w, h1, l1);
            int o = sr[p] * APx + sc[p];
            *(uint2*)&Ahp[o] = make_uint2(h0, h1);
            *(uint2*)&Alp[o] = make_uint2(l0, l1);
        }
        cp_wait0();        // B(kc) landed (issued before previous sync)
        __syncthreads();   // publishes A stage kc&1; retires readers of stage (kc+1)&1

        if (kc + 1 < NC) {
            issueB(kc + 1, (kc + 1) & 1); cp_commit();
#pragma unroll
            for (int p = 0; p < 4; ++p) {
                pA[p] += astep;
                pa[p] = *(const float4*)pA[p];
            }
        }

#pragma unroll
        for (int kb = 0; kb < 32; kb += 16) {
            unsigned bhf[2][4], blf[2][4];
            ldsm4(bhf[0], bBh + boff + kb * 2);
            ldsm4(bhf[1], bBh + boff + kb * 2 + 16 * BP * 2);
            ldsm4(blf[0], bBl + boff + kb * 2);
            ldsm4(blf[1], bBl + boff + kb * 2 + 16 * BP * 2);
#pragma unroll
            for (int i = 0; i < 2; ++i) {
                unsigned ah[4], al[4];
                if (isG1) {
                    unsigned o = aoff1 + (unsigned)(i * 16 * AP1 * 2 + kb * 2);
                    ldsm4(ah, bAh + o);
                    ldsm4(al, bAl + o);
                } else {
                    unsigned o = aoff2 + (unsigned)(kb * AP2 * 2 + i * 16 * 2);
                    ldsm4t(ah, bAh + o);
                    ldsm4t(al, bAl + o);
                }
#pragma unroll
                for (int j = 0; j < 4; ++j) {
                    const unsigned* bhp = &bhf[j >> 1][(j & 1) * 2];
                    const unsigned* blp = &blf[j >> 1][(j & 1) * 2];
                    mma_bf16(acc[i][j], ah, bhp);
                    mma_bf16(acc[i][j], ah, blp);
                    mma_bf16(acc[i][j], al, bhp);
                }
            }
        }
    }

    // epilogue: fp32 partial tile (128x64) -> g_part
    const int g = lane >> 2, q = lane & 3;
    const int gb = b * 2 + (isG1 ? 0 : 1);
    float* P = g_part + ((long)((gb * 16 + tile) * KSPLIT + ky)) * (128 * 64);
#pragma unroll
    for (int i = 0; i < 2; ++i)
#pragma unroll
        for (int j = 0; j < 4; ++j) {
            int r0 = mB + i * 16 + g;
            int c  = nB + j * 8 + 2 * q;
            *(float2*)&P[r0 * 64 + c]       = make_float2(acc[i][j][0], acc[i][j][1]);
            *(float2*)&P[(r0 + 8) * 64 + c] = make_float2(acc[i][j][2], acc[i][j][3]);
        }
}

// ---------------------------------------------------------------------------
// Kernel 1b: reduce split-K partials, split fp32 -> hi/lo bf16 factors.
// ---------------------------------------------------------------------------
__global__ void __launch_bounds__(256) reduce_kernel() {
    const int t  = blockIdx.x * 256 + threadIdx.x;   // 0 .. 262143
    const int t4 = t << 2;
    const int n    = t4 & 63;
    const int m    = (t4 >> 6) & 127;
    const int tile = (t4 >> 13) & 15;
    const int gb   = t4 >> 17;            // b*2 + gemm
    const int b    = gb >> 1;
    const int gemm = gb & 1;

    const float4* P = (const float4*)g_part +
                      ((long)(gb * 16 + tile) * KSPLIT * (128 * 64) + (m * 64 + n)) / 4;
    float4 s = P[0];
#pragma unroll
    for (int k = 1; k < KSPLIT; ++k) {
        float4 v = P[k * (128 * 64 / 4)];
        s.x += v.x; s.y += v.y; s.z += v.z; s.w += v.w;
    }

    unsigned h0, l0, h1, l1;
    split_pair(s.x, s.y, h0, l0);
    split_pair(s.z, s.w, h1, l1);

    const long base = ((long)b * SS + tile * 128 + m) * RR + n;  // SS == HH
    unsigned short* oh = gemm == 0 ? g_Fsh : g_Fhh;
    unsigned short* ol = gemm == 0 ? g_Fsl : g_Fhl;
    *(uint2*)&oh[base] = make_uint2(h0, h1);
    *(uint2*)&ol[base] = make_uint2(l0, l1);
}

// ---------------------------------------------------------------------------
// Kernel 2: Out_b = F_s[b] (S x 64) @ F_h[b]^T (64 x H), fp32 out.
// CTA 128x128, K=64 resident, 8 warps (warp 64x32). Both operands [rows][k=64].
// ---------------------------------------------------------------------------
#define OAP 72
#define OSM_AL (128 * OAP)
#define OSM_BH (2 * 128 * OAP)
#define OSM_BL (3 * 128 * OAP)
#define OSM_TOT_BYTES (4 * 128 * OAP * 2)  // 73728

__global__ void __launch_bounds__(256) out_kernel(float* __restrict__ Out) {
    extern __shared__ unsigned short sm[];
    unsigned short* Ah = sm;
    unsigned short* Al = sm + OSM_AL;
    unsigned short* Bh = sm + OSM_BH;
    unsigned short* Bl = sm + OSM_BL;

    const int b = blockIdx.z, s0 = blockIdx.y * 128, h0 = blockIdx.x * 128;
    const int tid = threadIdx.x;

    {
        const unsigned short* agh = g_Fsh + ((long)(b * SS + s0)) * RR;
        const unsigned short* agl = g_Fsl + ((long)(b * SS + s0)) * RR;
        const unsigned short* bgh = g_Fhh + ((long)(b * HH + h0)) * RR;
        const unsigned short* bgl = g_Fhl + ((long)(b * HH + h0)) * RR;
#pragma unroll
        for (int p = 0; p < 4; ++p) {
            int idx = tid + p * 256;
            int r = idx >> 3, c = (idx & 7) * 8;
            *(uint4*)&Ah[r * OAP + c] = *(const uint4*)&agh[r * RR + c];
            *(uint4*)&Al[r * OAP + c] = *(const uint4*)&agl[r * RR + c];
            *(uint4*)&Bh[r * OAP + c] = *(const uint4*)&bgh[r * RR + c];
            *(uint4*)&Bl[r * OAP + c] = *(const uint4*)&bgl[r * RR + c];
        }
    }
    __syncthreads();

    const int warpId = tid >> 5, lane = tid & 31;
    const int mB = (warpId >> 2) * 64, nB = (warpId & 3) * 32;

    const unsigned sAh = (unsigned)__cvta_generic_to_shared(Ah);
    const unsigned sAl = (unsigned)__cvta_generic_to_shared(Al);
    const unsigned sBh = (unsigned)__cvta_generic_to_shared(Bh);
    const unsigned sBl = (unsigned)__cvta_generic_to_shared(Bl);

    const unsigned aoff = 2 * ((mB + (lane & 15)) * OAP + (lane >> 4) * 8);
    const unsigned aH = sAh + aoff, aL = sAl + aoff;
    const unsigned boff = 2 * ((nB + (lane & 7) + ((lane & 16) >> 1)) * OAP + (lane & 8));
    const unsigned bH = sBh + boff, bL = sBl + boff;

    float acc[4][4][4];
#pragma unroll
    for (int i = 0; i < 4; ++i)
#pragma unroll
        for (int j = 0; j < 4; ++j)
#pragma unroll
            for (int t = 0; t < 4; ++t) acc[i][j][t] = 0.0f;

#pragma unroll
    for (int kb = 0; kb < 64; kb += 16) {
        unsigned bhf[2][4], blf[2][4];
        ldsm4(bhf[0], bH + kb * 2);
        ldsm4(bhf[1], bH + kb * 2 + 16 * OAP * 2);
        ldsm4(blf[0], bL + kb * 2);
        ldsm4(blf[1], bL + kb * 2 + 16 * OAP * 2);
#pragma unroll
        for (int i = 0; i < 4; ++i) {
            unsigned ah[4], al[4];
            ldsm4(ah, aH + kb * 2 + i * (16 * OAP * 2));
            ldsm4(al, aL + kb * 2 + i * (16 * OAP * 2));
#pragma unroll
            for (int j = 0; j < 4; ++j) {
                const unsigned* bhp = &bhf[j >> 1][(j & 1) * 2];
                const unsigned* blp = &blf[j >> 1][(j & 1) * 2];
                mma_bf16(acc[i][j], ah, bhp);
                mma_bf16(acc[i][j], ah, blp);
                mma_bf16(acc[i][j], al, bhp);
            }
        }
    }

    const int g = lane >> 2, q = lane & 3;
    float* O = Out + ((long)(b * SS + s0)) * HH + h0;
#pragma unroll
    for (int i = 0; i < 4; ++i)
#pragma unroll
        for (int j = 0; j < 4; ++j) {
            int r = mB + i * 16 + g;
            int c = nB + j * 8 + 2 * q;
            *(float2*)&O[(long)r * HH + c]       = make_float2(acc[i][j][0], acc[i][j][1]);
            *(float2*)&O[(long)(r + 8) * HH + c] = make_float2(acc[i][j][2], acc[i][j][3]);
        }
}

// ---------------------------------------------------------------------------
// Launch: inputs per metadata: hidden_states, grid_chw (unused), W_seq, W_hid
// ---------------------------------------------------------------------------
extern "C" void kernel_launch(void* const* d_in, const int* in_sizes, int n_in,
                              void* d_out, int out_size) {
    const float* X    = (const float*)d_in[0];
    const float* Wseq = (const float*)d_in[2];
    const float* Whid = (const float*)d_in[3];
    float* Out = (float*)d_out;

    cudaFuncSetAttribute(fact_kernel, cudaFuncAttributeMaxDynamicSharedMemorySize,
                         FSM_BYTES);
    cudaFuncSetAttribute(out_kernel, cudaFuncAttributeMaxDynamicSharedMemorySize,
                         OSM_TOT_BYTES);

    wsplit_kernel<<<128, 256>>>((const float4*)Wseq, (const float4*)Whid);
    fact_kernel<<<dim3(32, KSPLIT, BB), 256, FSM_BYTES>>>(X);
    reduce_kernel<<<1024, 256>>>();
    out_kernel<<<dim3(HH / 128, SS / 128, BB), 256, OSM_TOT_BYTES>>>(Out);
}